// round 2
// baseline (speedup 1.0000x reference)
#include <cuda_runtime.h>

#define NMAX 100000
#define EMAX 600000
#define HID 128
#define NG 256
#define BN_EPS 1e-5f

// ---------------- scratch (device globals; no allocs allowed) ----------------
__device__ float g_deg[NMAX];
__device__ float g_dinv[NMAX];
__device__ float g_h[NMAX * HID];     // layer input / output after BN+ReLU
__device__ float g_hls[NMAX * HID];   // (h@W) * dinv[row]
__device__ float g_agg[NMAX * HID];   // init = hls (self loop), scatter adds
__device__ float g_sums[NG * HID];
__device__ float g_cnts[NG];
__device__ float g_p[64];             // pocket embedding

// ---------------- degree / dinv ----------------
__global__ void k_zero_deg(int n) {
    int i = blockIdx.x * blockDim.x + threadIdx.x;
    if (i < n) g_deg[i] = 0.f;
}

__global__ void k_deg_scatter(const int* __restrict__ dst, int e) {
    int i = blockIdx.x * blockDim.x + threadIdx.x;
    if (i < e) atomicAdd(&g_deg[dst[i]], 1.f);
}

__global__ void k_dinv(int n) {
    int i = blockIdx.x * blockDim.x + threadIdx.x;
    if (i < n) g_dinv[i] = rsqrtf(g_deg[i] + 1.f);
}

// ---------------- layer 0 GEMM: x[N,7] @ W0[7,128], scaled by dinv ----------------
// one warp per node; lane covers 4 columns (float4)
__global__ void k_gemm7(const float* __restrict__ x, const float* __restrict__ W0, int n) {
    __shared__ float sW[7 * 128];
    for (int i = threadIdx.x; i < 7 * 128; i += blockDim.x) sW[i] = W0[i];
    __syncthreads();

    int warp = (blockIdx.x * blockDim.x + threadIdx.x) >> 5;
    int lane = threadIdx.x & 31;
    if (warp >= n) return;

    float xr[7];
#pragma unroll
    for (int k = 0; k < 7; k++) xr[k] = __ldg(x + warp * 7 + k);

    float4 acc = make_float4(0.f, 0.f, 0.f, 0.f);
#pragma unroll
    for (int k = 0; k < 7; k++) {
        float4 b = ((const float4*)(sW + k * 128))[lane];
        acc.x += xr[k] * b.x; acc.y += xr[k] * b.y;
        acc.z += xr[k] * b.z; acc.w += xr[k] * b.w;
    }
    float dv = g_dinv[warp];
    acc.x *= dv; acc.y *= dv; acc.z *= dv; acc.w *= dv;
    ((float4*)(g_hls + warp * HID))[lane] = acc;
    ((float4*)(g_agg + warp * HID))[lane] = acc;
}

// ---------------- 128x128 GEMM: g_h[N,128] @ W[128,128], scaled by dinv ----------
// Reads g_h DIRECTLY (device global) — never passed from host.
// block: 256 threads, 64-row tile. thread = (warp: 8 rows) x (lane: 4 cols)
__global__ void k_gemm128(const float* __restrict__ W, int n) {
    __shared__ float sW[32][128];      // [k][col]
    __shared__ float sA[32][68];       // [k][row] transposed, +4 pad

    const float* __restrict__ A = g_h;

    int row0 = blockIdx.x * 64;
    int tid = threadIdx.x;
    int lane = tid & 31, warp = tid >> 5;

    float acc[8][4];
#pragma unroll
    for (int i = 0; i < 8; i++)
#pragma unroll
        for (int j = 0; j < 4; j++) acc[i][j] = 0.f;

    for (int kt = 0; kt < 128; kt += 32) {
        // W tile: 32x128 floats = 1024 float4, 4 per thread
        const float4* Wv = (const float4*)(W + kt * 128);
        float4* sWv = (float4*)(&sW[0][0]);
#pragma unroll
        for (int i = 0; i < 4; i++) sWv[tid + 256 * i] = Wv[tid + 256 * i];
        // A tile 64 rows x 32 k, stored transposed
#pragma unroll
        for (int i = 0; i < 2; i++) {
            int idx = tid + 256 * i;
            int r = idx >> 3, c = idx & 7;
            int row = row0 + r;
            float4 v = make_float4(0.f, 0.f, 0.f, 0.f);
            if (row < n) v = ((const float4*)(A + (size_t)row * 128 + kt))[c];
            sA[c * 4 + 0][r] = v.x; sA[c * 4 + 1][r] = v.y;
            sA[c * 4 + 2][r] = v.z; sA[c * 4 + 3][r] = v.w;
        }
        __syncthreads();
#pragma unroll
        for (int k = 0; k < 32; k++) {
            float4 b = ((const float4*)(&sW[k][0]))[lane];
            float4 a0 = *((const float4*)(&sA[k][warp * 8]));
            float4 a1 = *((const float4*)(&sA[k][warp * 8 + 4]));
            float a[8] = {a0.x, a0.y, a0.z, a0.w, a1.x, a1.y, a1.z, a1.w};
            float bb[4] = {b.x, b.y, b.z, b.w};
#pragma unroll
            for (int i = 0; i < 8; i++)
#pragma unroll
                for (int j = 0; j < 4; j++) acc[i][j] += a[i] * bb[j];
        }
        __syncthreads();
    }
#pragma unroll
    for (int i = 0; i < 8; i++) {
        int row = row0 + warp * 8 + i;
        if (row < n) {
            float dv = g_dinv[row];
            float4 o = make_float4(acc[i][0] * dv, acc[i][1] * dv,
                                   acc[i][2] * dv, acc[i][3] * dv);
            ((float4*)(g_hls + (size_t)row * HID))[lane] = o;
            ((float4*)(g_agg + (size_t)row * HID))[lane] = o;
        }
    }
}

// ---------------- edge scatter: agg[dst] += hls[src] (pure add, norm folded) -----
// one warp per edge; lane handles a float4 chunk; vectorized red.add
__global__ void k_scatter(const int* __restrict__ src, const int* __restrict__ dst, int e) {
    int t = blockIdx.x * blockDim.x + threadIdx.x;
    int edge = t >> 5;
    if (edge >= e) return;
    int lane = t & 31;
    int s = __ldg(src + edge);
    int d = __ldg(dst + edge);
    float4 v = ((const float4*)(g_hls + (size_t)s * HID))[lane];
    float* p = g_agg + (size_t)d * HID + lane * 4;
    asm volatile("red.global.add.v4.f32 [%0], {%1, %2, %3, %4};"
                 :: "l"(p), "f"(v.x), "f"(v.y), "f"(v.z), "f"(v.w) : "memory");
}

// ---------------- BN + ReLU: h = relu(bn(agg*dinv + b)) ----------------
__global__ void k_post(const float* __restrict__ b, const float* __restrict__ gamma,
                       const float* __restrict__ beta, const float* __restrict__ mean,
                       const float* __restrict__ var, int n) {
    int idx = blockIdx.x * blockDim.x + threadIdx.x;   // float4 index
    int total = n * (HID / 4);
    if (idx >= total) return;
    int node = idx >> 5;          // HID/4 = 32 chunks per node
    int c4 = (idx & 31) * 4;
    float dv = g_dinv[node];
    float4 a = ((const float4*)g_agg)[idx];
    float4 o;
    float* out = (float*)&o;
    float* av = (float*)&a;
#pragma unroll
    for (int j = 0; j < 4; j++) {
        int c = c4 + j;
        float scale = gamma[c] * rsqrtf(var[c] + BN_EPS);
        float v = av[j] * dv + b[c];
        v = (v - mean[c]) * scale + beta[c];
        out[j] = fmaxf(v, 0.f);
    }
    ((float4*)g_h)[idx] = o;
}

// ---------------- pooling ----------------
__global__ void k_zero_pool() {
    int i = blockIdx.x * blockDim.x + threadIdx.x;
    if (i < NG * HID) g_sums[i] = 0.f;
    if (i < NG) g_cnts[i] = 0.f;
}

__global__ void k_pool(const int* __restrict__ batch, int n) {
    int start = blockIdx.x * 512;
    int end = min(n, start + 512);
    if (start >= n) return;
    int t = threadIdx.x;          // feature column, 128 threads
    int cur = batch[start];
    float acc = 0.f, cnt = 0.f;
    for (int node = start; node < end; node++) {
        int g = batch[node];
        if (g != cur) {
            atomicAdd(&g_sums[cur * HID + t], acc);
            if (t == 0) atomicAdd(&g_cnts[cur], cnt);
            acc = 0.f; cnt = 0.f; cur = g;
        }
        acc += g_h[(size_t)node * HID + t];
        cnt += 1.f;
    }
    atomicAdd(&g_sums[cur * HID + t], acc);
    if (t == 0) atomicAdd(&g_cnts[cur], cnt);
}

// ---------------- pocket MLP: 28 -> 64 -> 64 ----------------
__global__ void k_pocket(const float* __restrict__ pocket,
                         const float* __restrict__ pw1, const float* __restrict__ pb1,
                         const float* __restrict__ pw2, const float* __restrict__ pb2) {
    __shared__ float p1[64];
    int t = threadIdx.x;  // 64 threads
    float a = pb1[t];
    for (int k = 0; k < 28; k++) a += pocket[k] * pw1[k * 64 + t];
    p1[t] = fmaxf(a, 0.f);
    __syncthreads();
    float b = pb2[t];
    for (int k = 0; k < 64; k++) b += p1[k] * pw2[k * 64 + t];
    g_p[t] = b;
}

// ---------------- classifier: per-graph block, 192 -> 96 -> 1 ----------------
__global__ void k_classify(const float* __restrict__ cw1, const float* __restrict__ cb1,
                           const float* __restrict__ cw2, const float* __restrict__ cb2,
                           float* __restrict__ out) {
    __shared__ float emb[192];
    __shared__ float hid[96];
    int g = blockIdx.x;
    int t = threadIdx.x;  // 192 threads
    if (t < 128) {
        float cnt = fmaxf(g_cnts[g], 1.f);
        emb[t] = g_sums[g * HID + t] / cnt;
    } else {
        emb[t] = g_p[t - 128];
    }
    __syncthreads();
    if (t < 96) {
        float a = cb1[t];
#pragma unroll 4
        for (int c = 0; c < 192; c++) a += emb[c] * cw1[c * 96 + t];
        hid[t] = fmaxf(a, 0.f);
    }
    __syncthreads();
    if (t == 0) {
        float o = cb2[0];
        for (int j = 0; j < 96; j++) o += hid[j] * cw2[j];
        out[g] = o;
    }
}

// ---------------- launch ----------------
extern "C" void kernel_launch(void* const* d_in, const int* in_sizes, int n_in,
                              void* d_out, int out_size) {
    const float* x      = (const float*)d_in[0];
    const int*   ei     = (const int*)  d_in[1];
    const int*   batch  = (const int*)  d_in[2];
    const float* pocket = (const float*)d_in[3];
    const float* W0 = (const float*)d_in[4];
    const float* b0 = (const float*)d_in[5];
    const float* W1 = (const float*)d_in[6];
    const float* b1 = (const float*)d_in[7];
    const float* W2 = (const float*)d_in[8];
    const float* b2 = (const float*)d_in[9];
    const float* bn_gamma = (const float*)d_in[10];
    const float* bn_beta  = (const float*)d_in[11];
    const float* bn_mean  = (const float*)d_in[12];
    const float* bn_var   = (const float*)d_in[13];
    const float* pw1 = (const float*)d_in[14];
    const float* pb1 = (const float*)d_in[15];
    const float* pw2 = (const float*)d_in[16];
    const float* pb2 = (const float*)d_in[17];
    const float* cw1 = (const float*)d_in[18];
    const float* cb1 = (const float*)d_in[19];
    const float* cw2 = (const float*)d_in[20];
    const float* cb2 = (const float*)d_in[21];
    float* out = (float*)d_out;

    int n = in_sizes[0] / 7;       // 100000
    int e = in_sizes[1] / 2;       // 600000
    const int* src = ei;
    const int* dst = ei + e;

    // degree / dinv
    k_zero_deg<<<(n + 255) / 256, 256>>>(n);
    k_deg_scatter<<<(e + 255) / 256, 256>>>(dst, e);
    k_dinv<<<(n + 255) / 256, 256>>>(n);

    int scat_blocks = (e * 32 + 255) / 256;
    int post_blocks = (n * (HID / 4) + 255) / 256;

    // layer 0
    k_gemm7<<<(n + 7) / 8, 256>>>(x, W0, n);
    k_scatter<<<scat_blocks, 256>>>(src, dst, e);
    k_post<<<post_blocks, 256>>>(b0, bn_gamma, bn_beta, bn_mean, bn_var, n);
    // layer 1
    k_gemm128<<<(n + 63) / 64, 256>>>(W1, n);
    k_scatter<<<scat_blocks, 256>>>(src, dst, e);
    k_post<<<post_blocks, 256>>>(b1, bn_gamma + HID, bn_beta + HID, bn_mean + HID, bn_var + HID, n);
    // layer 2
    k_gemm128<<<(n + 63) / 64, 256>>>(W2, n);
    k_scatter<<<scat_blocks, 256>>>(src, dst, e);
    k_post<<<post_blocks, 256>>>(b2, bn_gamma + 2 * HID, bn_beta + 2 * HID, bn_mean + 2 * HID, bn_var + 2 * HID, n);

    // pooling + heads
    k_zero_pool<<<(NG * HID + 255) / 256, 256>>>();
    k_pool<<<(n + 511) / 512, 128>>>(batch, n);
    k_pocket<<<1, 64>>>(pocket, pw1, pb1, pw2, pb2);
    k_classify<<<NG, 192>>>(cw1, cb1, cw2, cb2, out);
}

// round 3
// speedup vs baseline: 1.2891x; 1.2891x over previous
#include <cuda_runtime.h>

#define NMAX 100000
#define EMAX 600000
#define HID 128
#define NG 256
#define BN_EPS 1e-5f
#define FULLMASK 0xffffffffu

// ---------------- scratch (device globals; no allocs allowed) ----------------
__device__ int   g_rowstart[NMAX + 1];  // CSR row offsets (by dst)
__device__ int   g_fill[NMAX];          // fill cursor
__device__ int   g_csr[EMAX];           // src indices grouped by dst
__device__ int   g_bsum[256];           // scan block sums
__device__ float g_dinv[NMAX];
__device__ float g_h[NMAX * HID];       // layer activations
__device__ float g_hls[NMAX * HID];     // (h@W) * dinv[row]
__device__ float g_sums[NG * HID];
__device__ float g_cnts[NG];
__device__ float g_p[64];               // pocket embedding

// ---------------- f32x2 helpers (sm_103a packed fp32 pipe) ----------------
__device__ __forceinline__ unsigned long long pk2(float x, float y) {
    unsigned long long r;
    asm("mov.b64 %0, {%1, %2};" : "=l"(r) : "f"(x), "f"(y));
    return r;
}
__device__ __forceinline__ void upk2(unsigned long long v, float& x, float& y) {
    asm("mov.b64 {%0, %1}, %2;" : "=f"(x), "=f"(y) : "l"(v));
}
__device__ __forceinline__ unsigned long long ffma2(unsigned long long a,
                                                    unsigned long long b,
                                                    unsigned long long c) {
    unsigned long long r;
    asm("fma.rn.f32x2 %0, %1, %2, %3;" : "=l"(r) : "l"(a), "l"(b), "l"(c));
    return r;
}

// ---------------- CSR build ----------------
__global__ void k_zero_rs(int L) {
    int i = blockIdx.x * blockDim.x + threadIdx.x;
    if (i < L) g_rowstart[i] = 0;
}

__global__ void k_hist(const int* __restrict__ dst, int e) {
    int i = blockIdx.x * blockDim.x + threadIdx.x;
    if (i < e) atomicAdd(&g_rowstart[dst[i] + 1], 1);
}

// phase 1: per-block (1024 elems) inclusive scan, in place; block total -> g_bsum
__global__ void k_scan1(int L) {
    __shared__ int wsum[8];
    __shared__ int woff[8];
    int t = threadIdx.x;
    int base = blockIdx.x * 1024;
    int i0 = base + t * 4;
    int v[4];
#pragma unroll
    for (int j = 0; j < 4; j++) v[j] = (i0 + j < L) ? g_rowstart[i0 + j] : 0;
    v[1] += v[0]; v[2] += v[1]; v[3] += v[2];
    int tsum = v[3];
    int lane = t & 31, w = t >> 5;
    int x = tsum;
#pragma unroll
    for (int o = 1; o < 32; o <<= 1) {
        int y = __shfl_up_sync(FULLMASK, x, o);
        if (lane >= o) x += y;
    }
    if (lane == 31) wsum[w] = x;
    __syncthreads();
    if (t == 0) {
        int s = 0;
        for (int k = 0; k < 8; k++) { woff[k] = s; s += wsum[k]; }
        g_bsum[blockIdx.x] = s;
    }
    __syncthreads();
    int ex = woff[w] + x - tsum;  // exclusive prefix of this thread within block
#pragma unroll
    for (int j = 0; j < 4; j++)
        if (i0 + j < L) g_rowstart[i0 + j] = ex + v[j];
}

// phase 2: single block exclusive scan of block sums (nb <= 128)
__global__ void k_scan2(int nb) {
    __shared__ int wsum[4];
    __shared__ int woff[4];
    int t = threadIdx.x;  // 128 threads
    int v = (t < nb) ? g_bsum[t] : 0;
    int lane = t & 31, w = t >> 5;
    int x = v;
#pragma unroll
    for (int o = 1; o < 32; o <<= 1) {
        int y = __shfl_up_sync(FULLMASK, x, o);
        if (lane >= o) x += y;
    }
    if (lane == 31) wsum[w] = x;
    __syncthreads();
    if (t == 0) {
        int s = 0;
        for (int k = 0; k < 4; k++) { woff[k] = s; s += wsum[k]; }
    }
    __syncthreads();
    if (t < nb) g_bsum[t] = woff[w] + x - v;  // exclusive
}

// phase 3: add block offsets; also seed g_fill with row starts
__global__ void k_scan3(int L, int n) {
    int t = threadIdx.x;
    int base = blockIdx.x * 1024;
    int off = g_bsum[blockIdx.x];
    int i0 = base + t * 4;
#pragma unroll
    for (int j = 0; j < 4; j++) {
        int idx = i0 + j;
        if (idx < L) {
            int val = g_rowstart[idx] + off;
            g_rowstart[idx] = val;
            if (idx < n) g_fill[idx] = val;
        }
    }
}

__global__ void k_dinv(int n) {
    int i = blockIdx.x * blockDim.x + threadIdx.x;
    if (i < n) {
        float deg = (float)(g_rowstart[i + 1] - g_rowstart[i]);
        g_dinv[i] = rsqrtf(deg + 1.f);
    }
}

__global__ void k_fill(const int* __restrict__ src, const int* __restrict__ dst, int e) {
    int i = blockIdx.x * blockDim.x + threadIdx.x;
    if (i < e) {
        int pos = atomicAdd(&g_fill[dst[i]], 1);
        g_csr[pos] = src[i];
    }
}

// ---------------- layer 0 GEMM: x[N,7] @ W0[7,128], scaled by dinv ----------------
__global__ void k_gemm7(const float* __restrict__ x, const float* __restrict__ W0, int n) {
    __shared__ float sW[7 * 128];
    for (int i = threadIdx.x; i < 7 * 128; i += blockDim.x) sW[i] = W0[i];
    __syncthreads();

    int warp = (blockIdx.x * blockDim.x + threadIdx.x) >> 5;
    int lane = threadIdx.x & 31;
    if (warp >= n) return;

    float xr[7];
#pragma unroll
    for (int k = 0; k < 7; k++) xr[k] = __ldg(x + warp * 7 + k);

    float4 acc = make_float4(0.f, 0.f, 0.f, 0.f);
#pragma unroll
    for (int k = 0; k < 7; k++) {
        float4 b = ((const float4*)(sW + k * 128))[lane];
        acc.x += xr[k] * b.x; acc.y += xr[k] * b.y;
        acc.z += xr[k] * b.z; acc.w += xr[k] * b.w;
    }
    float dv = g_dinv[warp];
    acc.x *= dv; acc.y *= dv; acc.z *= dv; acc.w *= dv;
    ((float4*)(g_hls + (size_t)warp * HID))[lane] = acc;
}

// ---------------- 128x128 GEMM: g_h @ W, scaled by dinv, f32x2 packed ----------
// block: 256 threads, 64-row tile. warp: 8 rows (as 4 row-pairs), lane: 4 cols
__global__ void k_gemm128(const float* __restrict__ W, int n) {
    __shared__ float sW[32][128];      // [k][col]
    __shared__ float sA[32][68];       // [k][row] transposed, +4 pad

    const float* __restrict__ A = g_h;

    int row0 = blockIdx.x * 64;
    int tid = threadIdx.x;
    int lane = tid & 31, warp = tid >> 5;

    unsigned long long acc2[4][4];     // [row-pair][col]
#pragma unroll
    for (int p = 0; p < 4; p++)
#pragma unroll
        for (int j = 0; j < 4; j++) acc2[p][j] = 0ull;

    for (int kt = 0; kt < 128; kt += 32) {
        const float4* Wv = (const float4*)(W + kt * 128);
        float4* sWv = (float4*)(&sW[0][0]);
#pragma unroll
        for (int i = 0; i < 4; i++) sWv[tid + 256 * i] = Wv[tid + 256 * i];
#pragma unroll
        for (int i = 0; i < 2; i++) {
            int idx = tid + 256 * i;
            int r = idx >> 3, c = idx & 7;
            int row = row0 + r;
            float4 v = make_float4(0.f, 0.f, 0.f, 0.f);
            if (row < n) v = ((const float4*)(A + (size_t)row * 128 + kt))[c];
            sA[c * 4 + 0][r] = v.x; sA[c * 4 + 1][r] = v.y;
            sA[c * 4 + 2][r] = v.z; sA[c * 4 + 3][r] = v.w;
        }
        __syncthreads();
#pragma unroll
        for (int k = 0; k < 32; k++) {
            float4 b = ((const float4*)(&sW[k][0]))[lane];
            unsigned long long bb[4];
            bb[0] = pk2(b.x, b.x); bb[1] = pk2(b.y, b.y);
            bb[2] = pk2(b.z, b.z); bb[3] = pk2(b.w, b.w);
            const unsigned long long* ap =
                (const unsigned long long*)(&sA[k][warp * 8]);
#pragma unroll
            for (int p = 0; p < 4; p++) {
                unsigned long long a = ap[p];   // rows (2p, 2p+1), broadcast in warp
#pragma unroll
                for (int j = 0; j < 4; j++) acc2[p][j] = ffma2(a, bb[j], acc2[p][j]);
            }
        }
        __syncthreads();
    }
#pragma unroll
    for (int p = 0; p < 4; p++) {
        float lo[4], hi[4];
#pragma unroll
        for (int j = 0; j < 4; j++) upk2(acc2[p][j], lo[j], hi[j]);
        int r0 = row0 + warp * 8 + 2 * p;
        int r1 = r0 + 1;
        if (r0 < n) {
            float dv = g_dinv[r0];
            ((float4*)(g_hls + (size_t)r0 * HID))[lane] =
                make_float4(lo[0] * dv, lo[1] * dv, lo[2] * dv, lo[3] * dv);
        }
        if (r1 < n) {
            float dv = g_dinv[r1];
            ((float4*)(g_hls + (size_t)r1 * HID))[lane] =
                make_float4(hi[0] * dv, hi[1] * dv, hi[2] * dv, hi[3] * dv);
        }
    }
}

// ------- fused gather-aggregate + BN + ReLU: h = relu(bn((sum_in + self)*dinv + b))
// one warp per dst node; lane covers 4 columns (float4)
__global__ void k_aggregate(const float* __restrict__ b, const float* __restrict__ gamma,
                            const float* __restrict__ beta, const float* __restrict__ mean,
                            const float* __restrict__ var, int n) {
    int warp = (blockIdx.x * blockDim.x + threadIdx.x) >> 5;
    int lane = threadIdx.x & 31;
    if (warp >= n) return;

    int s0 = g_rowstart[warp];
    int s1 = g_rowstart[warp + 1];
    int deg = s1 - s0;

    // self term
    float4 acc = __ldg((const float4*)(g_hls + (size_t)warp * HID) + lane);

    for (int j0 = 0; j0 < deg; j0 += 32) {
        int myidx = (s0 + j0 + lane < s1) ? __ldg(&g_csr[s0 + j0 + lane]) : 0;
        int m = min(32, deg - j0);
        for (int j = 0; j < m; j++) {
            int s = __shfl_sync(FULLMASK, myidx, j);
            float4 v = __ldg((const float4*)(g_hls + (size_t)s * HID) + lane);
            acc.x += v.x; acc.y += v.y; acc.z += v.z; acc.w += v.w;
        }
    }

    float dv = g_dinv[warp];
    int c4 = lane * 4;
    float out[4];
    float av[4] = {acc.x, acc.y, acc.z, acc.w};
#pragma unroll
    for (int j = 0; j < 4; j++) {
        int c = c4 + j;
        float scale = __ldg(gamma + c) * rsqrtf(__ldg(var + c) + BN_EPS);
        float v = av[j] * dv + __ldg(b + c);
        v = (v - __ldg(mean + c)) * scale + __ldg(beta + c);
        out[j] = fmaxf(v, 0.f);
    }
    ((float4*)(g_h + (size_t)warp * HID))[lane] =
        make_float4(out[0], out[1], out[2], out[3]);
}

// ---------------- pooling ----------------
__global__ void k_zero_pool() {
    int i = blockIdx.x * blockDim.x + threadIdx.x;
    if (i < NG * HID) g_sums[i] = 0.f;
    if (i < NG) g_cnts[i] = 0.f;
}

__global__ void k_pool(const int* __restrict__ batch, int n) {
    int start = blockIdx.x * 512;
    int end = min(n, start + 512);
    if (start >= n) return;
    int t = threadIdx.x;          // feature column, 128 threads
    int cur = batch[start];
    float acc = 0.f, cnt = 0.f;
    for (int node = start; node < end; node++) {
        int g = batch[node];
        if (g != cur) {
            atomicAdd(&g_sums[cur * HID + t], acc);
            if (t == 0) atomicAdd(&g_cnts[cur], cnt);
            acc = 0.f; cnt = 0.f; cur = g;
        }
        acc += g_h[(size_t)node * HID + t];
        cnt += 1.f;
    }
    atomicAdd(&g_sums[cur * HID + t], acc);
    if (t == 0) atomicAdd(&g_cnts[cur], cnt);
}

// ---------------- pocket MLP: 28 -> 64 -> 64 ----------------
__global__ void k_pocket(const float* __restrict__ pocket,
                         const float* __restrict__ pw1, const float* __restrict__ pb1,
                         const float* __restrict__ pw2, const float* __restrict__ pb2) {
    __shared__ float p1[64];
    int t = threadIdx.x;  // 64 threads
    float a = pb1[t];
    for (int k = 0; k < 28; k++) a += pocket[k] * pw1[k * 64 + t];
    p1[t] = fmaxf(a, 0.f);
    __syncthreads();
    float b = pb2[t];
    for (int k = 0; k < 64; k++) b += p1[k] * pw2[k * 64 + t];
    g_p[t] = b;
}

// ---------------- classifier: per-graph block, 192 -> 96 -> 1 ----------------
__global__ void k_classify(const float* __restrict__ cw1, const float* __restrict__ cb1,
                           const float* __restrict__ cw2, const float* __restrict__ cb2,
                           float* __restrict__ out) {
    __shared__ float emb[192];
    __shared__ float hid[96];
    int g = blockIdx.x;
    int t = threadIdx.x;  // 192 threads
    if (t < 128) {
        float cnt = fmaxf(g_cnts[g], 1.f);
        emb[t] = g_sums[g * HID + t] / cnt;
    } else {
        emb[t] = g_p[t - 128];
    }
    __syncthreads();
    if (t < 96) {
        float a = cb1[t];
#pragma unroll 4
        for (int c = 0; c < 192; c++) a += emb[c] * cw1[c * 96 + t];
        hid[t] = fmaxf(a, 0.f);
    }
    __syncthreads();
    if (t == 0) {
        float o = cb2[0];
        for (int j = 0; j < 96; j++) o += hid[j] * cw2[j];
        out[g] = o;
    }
}

// ---------------- launch ----------------
extern "C" void kernel_launch(void* const* d_in, const int* in_sizes, int n_in,
                              void* d_out, int out_size) {
    const float* x      = (const float*)d_in[0];
    const int*   ei     = (const int*)  d_in[1];
    const int*   batch  = (const int*)  d_in[2];
    const float* pocket = (const float*)d_in[3];
    const float* W0 = (const float*)d_in[4];
    const float* b0 = (const float*)d_in[5];
    const float* W1 = (const float*)d_in[6];
    const float* b1 = (const float*)d_in[7];
    const float* W2 = (const float*)d_in[8];
    const float* b2 = (const float*)d_in[9];
    const float* bn_gamma = (const float*)d_in[10];
    const float* bn_beta  = (const float*)d_in[11];
    const float* bn_mean  = (const float*)d_in[12];
    const float* bn_var   = (const float*)d_in[13];
    const float* pw1 = (const float*)d_in[14];
    const float* pb1 = (const float*)d_in[15];
    const float* pw2 = (const float*)d_in[16];
    const float* pb2 = (const float*)d_in[17];
    const float* cw1 = (const float*)d_in[18];
    const float* cb1 = (const float*)d_in[19];
    const float* cw2 = (const float*)d_in[20];
    const float* cb2 = (const float*)d_in[21];
    float* out = (float*)d_out;

    int n = in_sizes[0] / 7;       // 100000
    int e = in_sizes[1] / 2;       // 600000
    const int* src = ei;
    const int* dst = ei + e;

    int L = n + 1;
    int NB = (L + 1023) / 1024;    // 98

    // CSR build (by dst)
    k_zero_rs<<<(L + 255) / 256, 256>>>(L);
    k_hist<<<(e + 255) / 256, 256>>>(dst, e);
    k_scan1<<<NB, 256>>>(L);
    k_scan2<<<1, 128>>>(NB);
    k_scan3<<<NB, 256>>>(L, n);
    k_dinv<<<(n + 255) / 256, 256>>>(n);
    k_fill<<<(e + 255) / 256, 256>>>(src, dst, e);

    int agg_blocks = (n * 32 + 255) / 256;

    // layer 0
    k_gemm7<<<(n + 7) / 8, 256>>>(x, W0, n);
    k_aggregate<<<agg_blocks, 256>>>(b0, bn_gamma, bn_beta, bn_mean, bn_var, n);
    // layer 1
    k_gemm128<<<(n + 63) / 64, 256>>>(W1, n);
    k_aggregate<<<agg_blocks, 256>>>(b1, bn_gamma + HID, bn_beta + HID,
                                     bn_mean + HID, bn_var + HID, n);
    // layer 2
    k_gemm128<<<(n + 63) / 64, 256>>>(W2, n);
    k_aggregate<<<agg_blocks, 256>>>(b2, bn_gamma + 2 * HID, bn_beta + 2 * HID,
                                     bn_mean + 2 * HID, bn_var + 2 * HID, n);

    // pooling + heads
    k_zero_pool<<<(NG * HID + 255) / 256, 256>>>();
    k_pool<<<(n + 511) / 512, 128>>>(batch, n);
    k_pocket<<<1, 64>>>(pocket, pw1, pb1, pw2, pb2);
    k_classify<<<NG, 192>>>(cw1, cb1, cw2, cb2, out);
}

// round 5
// speedup vs baseline: 1.6953x; 1.3151x over previous
#include <cuda_runtime.h>

#define NMAX 100000
#define EMAX 600000
#define HID 128
#define NG 256
#define BN_EPS 1e-5f
#define FULLMASK 0xffffffffu

typedef unsigned long long ull;

// ---------------- scratch (device globals; no allocs allowed) ----------------
__device__ int   g_rowstart[NMAX + 1];  // CSR row offsets (by dst)
__device__ int   g_fill[NMAX];          // fill cursor
__device__ int   g_csr[EMAX];           // src indices grouped by dst
__device__ int   g_bsum[256];           // scan block sums
__device__ float g_dinv[NMAX];
__device__ float g_h[NMAX * HID];       // layer activations
__device__ float g_hls[NMAX * HID];     // (h@W) * dinv[row]
__device__ float g_sums[NG * HID];
__device__ float g_cnts[NG];
__device__ float g_p[64];               // pocket embedding

// ---------------- f32x2 helpers (sm_103a packed fp32 pipe) ----------------
__device__ __forceinline__ ull pk2(float x, float y) {
    ull r;
    asm("mov.b64 %0, {%1, %2};" : "=l"(r) : "f"(x), "f"(y));
    return r;
}
__device__ __forceinline__ void upk2(ull v, float& x, float& y) {
    asm("mov.b64 {%0, %1}, %2;" : "=f"(x), "=f"(y) : "l"(v));
}
__device__ __forceinline__ ull ffma2(ull a, ull b, ull c) {
    ull r;
    asm("fma.rn.f32x2 %0, %1, %2, %3;" : "=l"(r) : "l"(a), "l"(b), "l"(c));
    return r;
}
__device__ __forceinline__ ull fadd2(ull a, ull b) {
    ull r;
    asm("add.rn.f32x2 %0, %1, %2;" : "=l"(r) : "l"(a), "l"(b));
    return r;
}

// ---------------- CSR build ----------------
__global__ void k_zero_rs(int L) {
    int i = blockIdx.x * blockDim.x + threadIdx.x;
    if (i < L) g_rowstart[i] = 0;
}

__global__ void k_hist(const int* __restrict__ dst, int e) {
    int i = blockIdx.x * blockDim.x + threadIdx.x;
    if (i < e) atomicAdd(&g_rowstart[dst[i] + 1], 1);
}

// phase 1: per-block (1024 elems) inclusive scan, in place; block total -> g_bsum
__global__ void k_scan1(int L) {
    __shared__ int wsum[8];
    __shared__ int woff[8];
    int t = threadIdx.x;
    int base = blockIdx.x * 1024;
    int i0 = base + t * 4;
    int v[4];
#pragma unroll
    for (int j = 0; j < 4; j++) v[j] = (i0 + j < L) ? g_rowstart[i0 + j] : 0;
    v[1] += v[0]; v[2] += v[1]; v[3] += v[2];
    int tsum = v[3];
    int lane = t & 31, w = t >> 5;
    int x = tsum;
#pragma unroll
    for (int o = 1; o < 32; o <<= 1) {
        int y = __shfl_up_sync(FULLMASK, x, o);
        if (lane >= o) x += y;
    }
    if (lane == 31) wsum[w] = x;
    __syncthreads();
    if (t == 0) {
        int s = 0;
        for (int k = 0; k < 8; k++) { woff[k] = s; s += wsum[k]; }
        g_bsum[blockIdx.x] = s;
    }
    __syncthreads();
    int ex = woff[w] + x - tsum;
#pragma unroll
    for (int j = 0; j < 4; j++)
        if (i0 + j < L) g_rowstart[i0 + j] = ex + v[j];
}

// phase 2: single block exclusive scan of block sums (nb <= 128)
__global__ void k_scan2(int nb) {
    __shared__ int wsum[4];
    __shared__ int woff[4];
    int t = threadIdx.x;
    int v = (t < nb) ? g_bsum[t] : 0;
    int lane = t & 31, w = t >> 5;
    int x = v;
#pragma unroll
    for (int o = 1; o < 32; o <<= 1) {
        int y = __shfl_up_sync(FULLMASK, x, o);
        if (lane >= o) x += y;
    }
    if (lane == 31) wsum[w] = x;
    __syncthreads();
    if (t == 0) {
        int s = 0;
        for (int k = 0; k < 4; k++) { woff[k] = s; s += wsum[k]; }
    }
    __syncthreads();
    if (t < nb) g_bsum[t] = woff[w] + x - v;
}

// phase 3: add block offsets; seed g_fill with row starts
__global__ void k_scan3(int L, int n) {
    int t = threadIdx.x;
    int base = blockIdx.x * 1024;
    int off = g_bsum[blockIdx.x];
    int i0 = base + t * 4;
#pragma unroll
    for (int j = 0; j < 4; j++) {
        int idx = i0 + j;
        if (idx < L) {
            int val = g_rowstart[idx] + off;
            g_rowstart[idx] = val;
            if (idx < n) g_fill[idx] = val;
        }
    }
}

__global__ void k_fill(const int* __restrict__ src, const int* __restrict__ dst, int e) {
    int i = blockIdx.x * blockDim.x + threadIdx.x;
    if (i < e) {
        int pos = atomicAdd(&g_fill[dst[i]], 1);
        g_csr[pos] = src[i];
    }
}

// ---- layer 0 GEMM: x[N,7] @ W0[7,128], scaled by dinv; also computes dinv ----
__global__ void k_gemm7(const float* __restrict__ x, const float* __restrict__ W0, int n) {
    __shared__ float sW[7 * 128];
    for (int i = threadIdx.x; i < 7 * 128; i += blockDim.x) sW[i] = W0[i];
    __syncthreads();

    int warp = (blockIdx.x * blockDim.x + threadIdx.x) >> 5;
    int lane = threadIdx.x & 31;
    if (warp >= n) return;

    // dinv = rsqrt(deg+1), deg from CSR rowstart
    float deg = (float)(__ldg(&g_rowstart[warp + 1]) - __ldg(&g_rowstart[warp]));
    float dv = rsqrtf(deg + 1.f);
    if (lane == 0) g_dinv[warp] = dv;

    float xr[7];
#pragma unroll
    for (int k = 0; k < 7; k++) xr[k] = __ldg(x + warp * 7 + k);

    float4 acc = make_float4(0.f, 0.f, 0.f, 0.f);
#pragma unroll
    for (int k = 0; k < 7; k++) {
        float4 b = ((const float4*)(sW + k * 128))[lane];
        acc.x += xr[k] * b.x; acc.y += xr[k] * b.y;
        acc.z += xr[k] * b.z; acc.w += xr[k] * b.w;
    }
    acc.x *= dv; acc.y *= dv; acc.z *= dv; acc.w *= dv;
    ((float4*)(g_hls + (size_t)warp * HID))[lane] = acc;
}

// ---- 128x128 GEMM: g_h @ W, scaled by dinv, f32x2, 128-row tiles ----
// block: 256 threads (8 warps). warp -> 16 rows (8 row-pairs), lane -> 4 cols.
__global__ __launch_bounds__(256, 2) void k_gemm128(const float* __restrict__ W, int n) {
    __shared__ float sW[32][128];      // [k][col]
    __shared__ float sA[32][130];      // [k][row] transposed, stride 130 (2-way conf)

    const float* __restrict__ A = g_h;

    int row0 = blockIdx.x * 128;
    int tid = threadIdx.x;
    int lane = tid & 31, warp = tid >> 5;

    ull acc2[8][4];                    // [row-pair][col]
#pragma unroll
    for (int p = 0; p < 8; p++)
#pragma unroll
        for (int j = 0; j < 4; j++) acc2[p][j] = 0ull;

    for (int kt = 0; kt < 128; kt += 32) {
        const float4* Wv = (const float4*)(W + kt * 128);
        float4* sWv = (float4*)(&sW[0][0]);
#pragma unroll
        for (int i = 0; i < 4; i++) sWv[tid + 256 * i] = Wv[tid + 256 * i];
        // A tile: 128 rows x 32 k = 1024 float4, 4 per thread, stored transposed
#pragma unroll
        for (int i = 0; i < 4; i++) {
            int idx = tid + 256 * i;
            int r = idx >> 3, c = idx & 7;
            int row = row0 + r;
            float4 v = make_float4(0.f, 0.f, 0.f, 0.f);
            if (row < n) v = ((const float4*)(A + (size_t)row * 128 + kt))[c];
            sA[c * 4 + 0][r] = v.x; sA[c * 4 + 1][r] = v.y;
            sA[c * 4 + 2][r] = v.z; sA[c * 4 + 3][r] = v.w;
        }
        __syncthreads();
#pragma unroll 8
        for (int k = 0; k < 32; k++) {
            float4 b = ((const float4*)(&sW[k][0]))[lane];
            ull bb0 = pk2(b.x, b.x), bb1 = pk2(b.y, b.y);
            ull bb2 = pk2(b.z, b.z), bb3 = pk2(b.w, b.w);
            const ull* ap = (const ull*)(&sA[k][warp * 16]);
#pragma unroll
            for (int p = 0; p < 8; p++) {
                ull a = ap[p];         // rows (2p, 2p+1) of this warp's 16
                acc2[p][0] = ffma2(a, bb0, acc2[p][0]);
                acc2[p][1] = ffma2(a, bb1, acc2[p][1]);
                acc2[p][2] = ffma2(a, bb2, acc2[p][2]);
                acc2[p][3] = ffma2(a, bb3, acc2[p][3]);
            }
        }
        __syncthreads();
    }
#pragma unroll
    for (int p = 0; p < 8; p++) {
        float lo[4], hi[4];
#pragma unroll
        for (int j = 0; j < 4; j++) upk2(acc2[p][j], lo[j], hi[j]);
        int r0 = row0 + warp * 16 + 2 * p;
        int r1 = r0 + 1;
        if (r0 < n) {
            float dv = g_dinv[r0];
            ((float4*)(g_hls + (size_t)r0 * HID))[lane] =
                make_float4(lo[0] * dv, lo[1] * dv, lo[2] * dv, lo[3] * dv);
        }
        if (r1 < n) {
            float dv = g_dinv[r1];
            ((float4*)(g_hls + (size_t)r1 * HID))[lane] =
                make_float4(hi[0] * dv, hi[1] * dv, hi[2] * dv, hi[3] * dv);
        }
    }
}

// ------- fused gather-aggregate + BN + ReLU, 4-edge unrolled, f32x2 adds -------
// one warp per dst node; lane covers 4 columns (float4)
__global__ void k_aggregate(const float* __restrict__ b, const float* __restrict__ gamma,
                            const float* __restrict__ beta, const float* __restrict__ mean,
                            const float* __restrict__ var, int n) {
    int warp = (blockIdx.x * blockDim.x + threadIdx.x) >> 5;
    int lane = threadIdx.x & 31;
    if (warp >= n) return;

    int s0 = g_rowstart[warp];
    int s1 = g_rowstart[warp + 1];

    union F4 { float4 f; ull u[2]; };

    // self term
    F4 self; self.f = __ldg((const float4*)(g_hls + (size_t)warp * HID) + lane);
    ull acc0 = self.u[0], acc1 = self.u[1];

    for (int j0 = s0; j0 < s1; j0 += 32) {
        int myidx = (j0 + lane < s1) ? __ldg(&g_csr[j0 + lane]) : 0;
        int m = min(32, s1 - j0);
        int j = 0;
        for (; j + 4 <= m; j += 4) {
            int i0 = __shfl_sync(FULLMASK, myidx, j);
            int i1 = __shfl_sync(FULLMASK, myidx, j + 1);
            int i2 = __shfl_sync(FULLMASK, myidx, j + 2);
            int i3 = __shfl_sync(FULLMASK, myidx, j + 3);
            F4 v0, v1, v2, v3;
            v0.f = __ldg((const float4*)(g_hls + (size_t)i0 * HID) + lane);
            v1.f = __ldg((const float4*)(g_hls + (size_t)i1 * HID) + lane);
            v2.f = __ldg((const float4*)(g_hls + (size_t)i2 * HID) + lane);
            v3.f = __ldg((const float4*)(g_hls + (size_t)i3 * HID) + lane);
            acc0 = fadd2(acc0, fadd2(v0.u[0], v1.u[0]));
            acc1 = fadd2(acc1, fadd2(v0.u[1], v1.u[1]));
            acc0 = fadd2(acc0, fadd2(v2.u[0], v3.u[0]));
            acc1 = fadd2(acc1, fadd2(v2.u[1], v3.u[1]));
        }
        for (; j < m; j++) {
            int s = __shfl_sync(FULLMASK, myidx, j);
            F4 v; v.f = __ldg((const float4*)(g_hls + (size_t)s * HID) + lane);
            acc0 = fadd2(acc0, v.u[0]);
            acc1 = fadd2(acc1, v.u[1]);
        }
    }

    float dv = g_dinv[warp];
    int c4 = lane * 4;
    float av[4];
    upk2(acc0, av[0], av[1]);
    upk2(acc1, av[2], av[3]);
    float4 gm = __ldg((const float4*)(gamma) + lane);
    float4 vr = __ldg((const float4*)(var) + lane);
    float4 bi = __ldg((const float4*)(b) + lane);
    float4 mn = __ldg((const float4*)(mean) + lane);
    float4 bt = __ldg((const float4*)(beta) + lane);
    float gmv[4] = {gm.x, gm.y, gm.z, gm.w};
    float vrv[4] = {vr.x, vr.y, vr.z, vr.w};
    float biv[4] = {bi.x, bi.y, bi.z, bi.w};
    float mnv[4] = {mn.x, mn.y, mn.z, mn.w};
    float btv[4] = {bt.x, bt.y, bt.z, bt.w};
    float out[4];
#pragma unroll
    for (int j = 0; j < 4; j++) {
        float scale = gmv[j] * rsqrtf(vrv[j] + BN_EPS);
        float v = av[j] * dv + biv[j];
        v = (v - mnv[j]) * scale + btv[j];
        out[j] = fmaxf(v, 0.f);
    }
    (void)c4;
    ((float4*)(g_h + (size_t)warp * HID))[lane] =
        make_float4(out[0], out[1], out[2], out[3]);
}

// ---------------- pooling ----------------
__global__ void k_zero_pool() {
    int i = blockIdx.x * blockDim.x + threadIdx.x;
    if (i < NG * HID) g_sums[i] = 0.f;
    if (i < NG) g_cnts[i] = 0.f;
}

__global__ void k_pool(const int* __restrict__ batch, int n) {
    int start = blockIdx.x * 256;
    int end = min(n, start + 256);
    if (start >= n) return;
    int t = threadIdx.x;          // feature column, 128 threads
    int cur = batch[start];
    float acc = 0.f, cnt = 0.f;
    for (int node = start; node < end; node++) {
        int g = batch[node];
        if (g != cur) {
            atomicAdd(&g_sums[cur * HID + t], acc);
            if (t == 0) atomicAdd(&g_cnts[cur], cnt);
            acc = 0.f; cnt = 0.f; cur = g;
        }
        acc += g_h[(size_t)node * HID + t];
        cnt += 1.f;
    }
    atomicAdd(&g_sums[cur * HID + t], acc);
    if (t == 0) atomicAdd(&g_cnts[cur], cnt);
}

// ---------------- pocket MLP: 28 -> 64 -> 64 ----------------
__global__ void k_pocket(const float* __restrict__ pocket,
                         const float* __restrict__ pw1, const float* __restrict__ pb1,
                         const float* __restrict__ pw2, const float* __restrict__ pb2) {
    __shared__ float p1[64];
    int t = threadIdx.x;  // 64 threads
    float a = pb1[t];
    for (int k = 0; k < 28; k++) a += pocket[k] * pw1[k * 64 + t];
    p1[t] = fmaxf(a, 0.f);
    __syncthreads();
    float b = pb2[t];
    for (int k = 0; k < 64; k++) b += p1[k] * pw2[k * 64 + t];
    g_p[t] = b;
}

// ---------------- classifier: per-graph block, 192 -> 96 -> 1 ----------------
__global__ void k_classify(const float* __restrict__ cw1, const float* __restrict__ cb1,
                           const float* __restrict__ cw2, const float* __restrict__ cb2,
                           float* __restrict__ out) {
    __shared__ float emb[192];
    __shared__ float hid[96];
    int g = blockIdx.x;
    int t = threadIdx.x;  // 192 threads
    if (t < 128) {
        float cnt = fmaxf(g_cnts[g], 1.f);
        emb[t] = g_sums[g * HID + t] / cnt;
    } else {
        emb[t] = g_p[t - 128];
    }
    __syncthreads();
    if (t < 96) {
        float a = cb1[t];
#pragma unroll 4
        for (int c = 0; c < 192; c++) a += emb[c] * cw1[c * 96 + t];
        hid[t] = fmaxf(a, 0.f);
    }
    __syncthreads();
    if (t == 0) {
        float o = cb2[0];
        for (int j = 0; j < 96; j++) o += hid[j] * cw2[j];
        out[g] = o;
    }
}

// ---------------- launch ----------------
extern "C" void kernel_launch(void* const* d_in, const int* in_sizes, int n_in,
                              void* d_out, int out_size) {
    const float* x      = (const float*)d_in[0];
    const int*   ei     = (const int*)  d_in[1];
    const int*   batch  = (const int*)  d_in[2];
    const float* pocket = (const float*)d_in[3];
    const float* W0 = (const float*)d_in[4];
    const float* b0 = (const float*)d_in[5];
    const float* W1 = (const float*)d_in[6];
    const float* b1 = (const float*)d_in[7];
    const float* W2 = (const float*)d_in[8];
    const float* b2 = (const float*)d_in[9];
    const float* bn_gamma = (const float*)d_in[10];
    const float* bn_beta  = (const float*)d_in[11];
    const float* bn_mean  = (const float*)d_in[12];
    const float* bn_var   = (const float*)d_in[13];
    const float* pw1 = (const float*)d_in[14];
    const float* pb1 = (const float*)d_in[15];
    const float* pw2 = (const float*)d_in[16];
    const float* pb2 = (const float*)d_in[17];
    const float* cw1 = (const float*)d_in[18];
    const float* cb1 = (const float*)d_in[19];
    const float* cw2 = (const float*)d_in[20];
    const float* cb2 = (const float*)d_in[21];
    float* out = (float*)d_out;

    int n = in_sizes[0] / 7;       // 100000
    int e = in_sizes[1] / 2;       // 600000
    const int* src = ei;
    const int* dst = ei + e;

    int L = n + 1;
    int NB = (L + 1023) / 1024;    // 98

    // CSR build (by dst)
    k_zero_rs<<<(L + 255) / 256, 256>>>(L);
    k_hist<<<(e + 255) / 256, 256>>>(dst, e);
    k_scan1<<<NB, 256>>>(L);
    k_scan2<<<1, 128>>>(NB);
    k_scan3<<<NB, 256>>>(L, n);
    k_fill<<<(e + 255) / 256, 256>>>(src, dst, e);

    int agg_blocks = (n * 32 + 255) / 256;

    // layer 0 (gemm7 also computes dinv)
    k_gemm7<<<(n + 7) / 8, 256>>>(x, W0, n);
    k_aggregate<<<agg_blocks, 256>>>(b0, bn_gamma, bn_beta, bn_mean, bn_var, n);
    // layer 1
    k_gemm128<<<(n + 127) / 128, 256>>>(W1, n);
    k_aggregate<<<agg_blocks, 256>>>(b1, bn_gamma + HID, bn_beta + HID,
                                     bn_mean + HID, bn_var + HID, n);
    // layer 2
    k_gemm128<<<(n + 127) / 128, 256>>>(W2, n);
    k_aggregate<<<agg_blocks, 256>>>(b2, bn_gamma + 2 * HID, bn_beta + 2 * HID,
                                     bn_mean + 2 * HID, bn_var + 2 * HID, n);

    // pooling + heads
    k_zero_pool<<<(NG * HID + 255) / 256, 256>>>();
    k_pool<<<(n + 255) / 256, 128>>>(batch, n);
    k_pocket<<<1, 64>>>(pocket, pw1, pb1, pw2, pb2);
    k_classify<<<NG, 192>>>(cw1, cb1, cw2, cb2, out);
}

// round 8
// speedup vs baseline: 1.7749x; 1.0470x over previous
#include <cuda_runtime.h>

#define NMAX 100000
#define EMAX 600000
#define HID 128
#define NG 256
#define BN_EPS 1e-5f
#define FULLMASK 0xffffffffu

typedef unsigned long long ull;

// ---------------- scratch (device globals; no allocs allowed) ----------------
__device__ int   g_rowstart[NMAX + 1];  // CSR row offsets (by dst)
__device__ int   g_fill[NMAX];          // fill cursor
__device__ int   g_csr[EMAX];           // src indices grouped by dst
__device__ int   g_bsum[256];           // scan block sums
__device__ float g_dinv[NMAX];
__device__ float g_xs[NMAX * 8];        // x * dinv, padded to 8 floats
__device__ float g_h[NMAX * HID];       // layer activations
__device__ float g_hls[NMAX * HID];     // (h@W) * dinv[row]
__device__ float g_sums[NG * HID];
__device__ float g_cnts[NG];

// ---------------- f32x2 helpers (sm_103a packed fp32 pipe) ----------------
__device__ __forceinline__ ull pk2(float x, float y) {
    ull r;
    asm("mov.b64 %0, {%1, %2};" : "=l"(r) : "f"(x), "f"(y));
    return r;
}
__device__ __forceinline__ void upk2(ull v, float& x, float& y) {
    asm("mov.b64 {%0, %1}, %2;" : "=f"(x), "=f"(y) : "l"(v));
}
__device__ __forceinline__ ull ffma2(ull a, ull b, ull c) {
    ull r;
    asm("fma.rn.f32x2 %0, %1, %2, %3;" : "=l"(r) : "l"(a), "l"(b), "l"(c));
    return r;
}
__device__ __forceinline__ ull fadd2(ull a, ull b) {
    ull r;
    asm("add.rn.f32x2 %0, %1, %2;" : "=l"(r) : "l"(a), "l"(b));
    return r;
}

// ---------------- CSR build ----------------
__global__ void k_zero_rs(int L) {
    int i = blockIdx.x * blockDim.x + threadIdx.x;
    if (i < L) g_rowstart[i] = 0;
}

__global__ void k_hist(const int* __restrict__ dst, int e) {
    int i = blockIdx.x * blockDim.x + threadIdx.x;
    if (i < e) atomicAdd(&g_rowstart[dst[i] + 1], 1);
}

// phase 1: per-block (1024 elems) inclusive scan, in place; block total -> g_bsum
// Also emits dinv: pre-scan value at index i+1 is the degree of node i.
__global__ void k_scan1(int L, int n) {
    __shared__ int wsum[8];
    __shared__ int woff[8];
    int t = threadIdx.x;
    int base = blockIdx.x * 1024;
    int i0 = base + t * 4;
    int v[4];
#pragma unroll
    for (int j = 0; j < 4; j++) {
        int idx = i0 + j;
        v[j] = (idx < L) ? g_rowstart[idx] : 0;
        if (idx >= 1 && idx <= n) g_dinv[idx - 1] = rsqrtf((float)v[j] + 1.f);
    }
    v[1] += v[0]; v[2] += v[1]; v[3] += v[2];
    int tsum = v[3];
    int lane = t & 31, w = t >> 5;
    int x = tsum;
#pragma unroll
    for (int o = 1; o < 32; o <<= 1) {
        int y = __shfl_up_sync(FULLMASK, x, o);
        if (lane >= o) x += y;
    }
    if (lane == 31) wsum[w] = x;
    __syncthreads();
    if (t == 0) {
        int s = 0;
        for (int k = 0; k < 8; k++) { woff[k] = s; s += wsum[k]; }
        g_bsum[blockIdx.x] = s;
    }
    __syncthreads();
    int ex = woff[w] + x - tsum;
#pragma unroll
    for (int j = 0; j < 4; j++)
        if (i0 + j < L) g_rowstart[i0 + j] = ex + v[j];
}

// phase 2: single block exclusive scan of block sums (nb <= 128)
__global__ void k_scan2(int nb) {
    __shared__ int wsum[4];
    __shared__ int woff[4];
    int t = threadIdx.x;
    int v = (t < nb) ? g_bsum[t] : 0;
    int lane = t & 31, w = t >> 5;
    int x = v;
#pragma unroll
    for (int o = 1; o < 32; o <<= 1) {
        int y = __shfl_up_sync(FULLMASK, x, o);
        if (lane >= o) x += y;
    }
    if (lane == 31) wsum[w] = x;
    __syncthreads();
    if (t == 0) {
        int s = 0;
        for (int k = 0; k < 4; k++) { woff[k] = s; s += wsum[k]; }
    }
    __syncthreads();
    if (t < nb) g_bsum[t] = woff[w] + x - v;
}

// phase 3: add block offsets; seed g_fill with row starts
__global__ void k_scan3(int L, int n) {
    int t = threadIdx.x;
    int base = blockIdx.x * 1024;
    int off = g_bsum[blockIdx.x];
    int i0 = base + t * 4;
#pragma unroll
    for (int j = 0; j < 4; j++) {
        int idx = i0 + j;
        if (idx < L) {
            int val = g_rowstart[idx] + off;
            g_rowstart[idx] = val;
            if (idx < n) g_fill[idx] = val;
        }
    }
}

__global__ void k_fill(const int* __restrict__ src, const int* __restrict__ dst, int e) {
    int i = blockIdx.x * blockDim.x + threadIdx.x;
    if (i < e) {
        int pos = atomicAdd(&g_fill[dst[i]], 1);
        g_csr[pos] = src[i];
    }
}

// ---- prep: xs = x * dinv padded to 8 floats; also zero pooling buffers ----
__global__ void k_prep(const float* __restrict__ x, int n) {
    int i = blockIdx.x * blockDim.x + threadIdx.x;
    if (i < n * 8) {
        int node = i >> 3, k = i & 7;
        float v = (k < 7) ? x[node * 7 + k] * g_dinv[node] : 0.f;
        g_xs[i] = v;
    }
    if (i < NG * HID) g_sums[i] = 0.f;
    if (i < NG) g_cnts[i] = 0.f;
}

// ---- layer 0 fused: aggregate xs (8-dim) -> GEMM 8x128 -> BN -> ReLU -> g_h ----
// one warp per dst node. gather: 16 edges/iter, 2 lanes per edge (float4 each).
__global__ void k_layer0(const float* __restrict__ W0, const float* __restrict__ b0,
                         const float* __restrict__ gamma, const float* __restrict__ beta,
                         const float* __restrict__ mean, const float* __restrict__ var,
                         int n) {
    __shared__ float sW[8 * 128];   // row 7 zero-padded
    for (int i = threadIdx.x; i < 8 * 128; i += blockDim.x)
        sW[i] = (i < 7 * 128) ? W0[i] : 0.f;
    __syncthreads();

    int warp = (blockIdx.x * blockDim.x + threadIdx.x) >> 5;
    int lane = threadIdx.x & 31;
    if (warp >= n) return;

    int s0 = g_rowstart[warp];
    int s1 = g_rowstart[warp + 1];
    float dv = g_dinv[warp];
    int half = lane & 1;            // which float4 of the 8-float row
    int sub = lane >> 1;            // edge slot 0..15

    float4 acc = make_float4(0.f, 0.f, 0.f, 0.f);
    for (int j0 = s0; j0 < s1; j0 += 32) {
        int myidx = (j0 + lane < s1) ? __ldg(&g_csr[j0 + lane]) : 0;
        int m = min(32, s1 - j0);
#pragma unroll
        for (int base = 0; base < 32; base += 16) {
            if (base >= m) break;
            int e = base + sub;
            int s = __shfl_sync(FULLMASK, myidx, e);
            if (e < m) {
                float4 v = __ldg((const float4*)(g_xs + (size_t)s * 8) + half);
                acc.x += v.x; acc.y += v.y; acc.z += v.z; acc.w += v.w;
            }
        }
    }
    // reduce across lanes of same parity (16 lanes each)
#pragma unroll
    for (int off = 2; off < 32; off <<= 1) {
        acc.x += __shfl_down_sync(FULLMASK, acc.x, off);
        acc.y += __shfl_down_sync(FULLMASK, acc.y, off);
        acc.z += __shfl_down_sync(FULLMASK, acc.z, off);
        acc.w += __shfl_down_sync(FULLMASK, acc.w, off);
    }
    // lanes 0,1 hold halves; add self term (xs[dst], one dv already folded)
    // total = (sum_neighbors xs + xs[dst]) * dinv[dst]
    if (lane < 2) {
        float4 self = __ldg((const float4*)(g_xs + (size_t)warp * 8) + lane);
        acc.x = (acc.x + self.x) * dv;
        acc.y = (acc.y + self.y) * dv;
        acc.z = (acc.z + self.z) * dv;
        acc.w = (acc.w + self.w) * dv;
    }
    // broadcast the 8 aggregated values to all lanes
    float xa[8];
    xa[0] = __shfl_sync(FULLMASK, acc.x, 0);
    xa[1] = __shfl_sync(FULLMASK, acc.y, 0);
    xa[2] = __shfl_sync(FULLMASK, acc.z, 0);
    xa[3] = __shfl_sync(FULLMASK, acc.w, 0);
    xa[4] = __shfl_sync(FULLMASK, acc.x, 1);
    xa[5] = __shfl_sync(FULLMASK, acc.y, 1);
    xa[6] = __shfl_sync(FULLMASK, acc.z, 1);
    xa[7] = __shfl_sync(FULLMASK, acc.w, 1);

    // GEMM: 8 x 128, lane covers 4 columns
    float4 r = make_float4(0.f, 0.f, 0.f, 0.f);
#pragma unroll
    for (int k = 0; k < 8; k++) {
        float4 w = ((const float4*)(sW + k * 128))[lane];
        r.x += xa[k] * w.x; r.y += xa[k] * w.y;
        r.z += xa[k] * w.z; r.w += xa[k] * w.w;
    }
    // + bias, BN, ReLU
    float4 gm = __ldg((const float4*)gamma + lane);
    float4 vr = __ldg((const float4*)var + lane);
    float4 bi = __ldg((const float4*)b0 + lane);
    float4 mn = __ldg((const float4*)mean + lane);
    float4 bt = __ldg((const float4*)beta + lane);
    float rv[4] = {r.x, r.y, r.z, r.w};
    float gmv[4] = {gm.x, gm.y, gm.z, gm.w};
    float vrv[4] = {vr.x, vr.y, vr.z, vr.w};
    float biv[4] = {bi.x, bi.y, bi.z, bi.w};
    float mnv[4] = {mn.x, mn.y, mn.z, mn.w};
    float btv[4] = {bt.x, bt.y, bt.z, bt.w};
    float out[4];
#pragma unroll
    for (int j = 0; j < 4; j++) {
        float scale = gmv[j] * rsqrtf(vrv[j] + BN_EPS);
        float v = rv[j] + biv[j];
        v = (v - mnv[j]) * scale + btv[j];
        out[j] = fmaxf(v, 0.f);
    }
    ((float4*)(g_h + (size_t)warp * HID))[lane] =
        make_float4(out[0], out[1], out[2], out[3]);
}

// ---- 128x128 GEMM: g_h @ W, scaled by dinv, f32x2, 128-row tiles ----
__global__ __launch_bounds__(256, 2) void k_gemm128(const float* __restrict__ W, int n) {
    __shared__ float sW[32][128];
    __shared__ float sA[32][130];

    const float* __restrict__ A = g_h;

    int row0 = blockIdx.x * 128;
    int tid = threadIdx.x;
    int lane = tid & 31, warp = tid >> 5;

    ull acc2[8][4];
#pragma unroll
    for (int p = 0; p < 8; p++)
#pragma unroll
        for (int j = 0; j < 4; j++) acc2[p][j] = 0ull;

    for (int kt = 0; kt < 128; kt += 32) {
        const float4* Wv = (const float4*)(W + kt * 128);
        float4* sWv = (float4*)(&sW[0][0]);
#pragma unroll
        for (int i = 0; i < 4; i++) sWv[tid + 256 * i] = Wv[tid + 256 * i];
#pragma unroll
        for (int i = 0; i < 4; i++) {
            int idx = tid + 256 * i;
            int r = idx >> 3, c = idx & 7;
            int row = row0 + r;
            float4 v = make_float4(0.f, 0.f, 0.f, 0.f);
            if (row < n) v = ((const float4*)(A + (size_t)row * 128 + kt))[c];
            sA[c * 4 + 0][r] = v.x; sA[c * 4 + 1][r] = v.y;
            sA[c * 4 + 2][r] = v.z; sA[c * 4 + 3][r] = v.w;
        }
        __syncthreads();
#pragma unroll 8
        for (int k = 0; k < 32; k++) {
            float4 b = ((const float4*)(&sW[k][0]))[lane];
            ull bb0 = pk2(b.x, b.x), bb1 = pk2(b.y, b.y);
            ull bb2 = pk2(b.z, b.z), bb3 = pk2(b.w, b.w);
            const ull* ap = (const ull*)(&sA[k][warp * 16]);
#pragma unroll
            for (int p = 0; p < 8; p++) {
                ull a = ap[p];
                acc2[p][0] = ffma2(a, bb0, acc2[p][0]);
                acc2[p][1] = ffma2(a, bb1, acc2[p][1]);
                acc2[p][2] = ffma2(a, bb2, acc2[p][2]);
                acc2[p][3] = ffma2(a, bb3, acc2[p][3]);
            }
        }
        __syncthreads();
    }
#pragma unroll
    for (int p = 0; p < 8; p++) {
        float lo[4], hi[4];
#pragma unroll
        for (int j = 0; j < 4; j++) upk2(acc2[p][j], lo[j], hi[j]);
        int r0 = row0 + warp * 16 + 2 * p;
        int r1 = r0 + 1;
        if (r0 < n) {
            float dv = g_dinv[r0];
            ((float4*)(g_hls + (size_t)r0 * HID))[lane] =
                make_float4(lo[0] * dv, lo[1] * dv, lo[2] * dv, lo[3] * dv);
        }
        if (r1 < n) {
            float dv = g_dinv[r1];
            ((float4*)(g_hls + (size_t)r1 * HID))[lane] =
                make_float4(hi[0] * dv, hi[1] * dv, hi[2] * dv, hi[3] * dv);
        }
    }
}

// ------- fused gather-aggregate + BN + ReLU, 4-edge unrolled, f32x2 adds -------
__global__ void k_aggregate(const float* __restrict__ b, const float* __restrict__ gamma,
                            const float* __restrict__ beta, const float* __restrict__ mean,
                            const float* __restrict__ var, int n) {
    int warp = (blockIdx.x * blockDim.x + threadIdx.x) >> 5;
    int lane = threadIdx.x & 31;
    if (warp >= n) return;

    int s0 = g_rowstart[warp];
    int s1 = g_rowstart[warp + 1];

    union F4 { float4 f; ull u[2]; };

    F4 self; self.f = __ldg((const float4*)(g_hls + (size_t)warp * HID) + lane);
    ull acc0 = self.u[0], acc1 = self.u[1];

    for (int j0 = s0; j0 < s1; j0 += 32) {
        int myidx = (j0 + lane < s1) ? __ldg(&g_csr[j0 + lane]) : 0;
        int m = min(32, s1 - j0);
        int j = 0;
        for (; j + 4 <= m; j += 4) {
            int i0 = __shfl_sync(FULLMASK, myidx, j);
            int i1 = __shfl_sync(FULLMASK, myidx, j + 1);
            int i2 = __shfl_sync(FULLMASK, myidx, j + 2);
            int i3 = __shfl_sync(FULLMASK, myidx, j + 3);
            F4 v0, v1, v2, v3;
            v0.f = __ldg((const float4*)(g_hls + (size_t)i0 * HID) + lane);
            v1.f = __ldg((const float4*)(g_hls + (size_t)i1 * HID) + lane);
            v2.f = __ldg((const float4*)(g_hls + (size_t)i2 * HID) + lane);
            v3.f = __ldg((const float4*)(g_hls + (size_t)i3 * HID) + lane);
            acc0 = fadd2(acc0, fadd2(v0.u[0], v1.u[0]));
            acc1 = fadd2(acc1, fadd2(v0.u[1], v1.u[1]));
            acc0 = fadd2(acc0, fadd2(v2.u[0], v3.u[0]));
            acc1 = fadd2(acc1, fadd2(v2.u[1], v3.u[1]));
        }
        for (; j < m; j++) {
            int s = __shfl_sync(FULLMASK, myidx, j);
            F4 v; v.f = __ldg((const float4*)(g_hls + (size_t)s * HID) + lane);
            acc0 = fadd2(acc0, v.u[0]);
            acc1 = fadd2(acc1, v.u[1]);
        }
    }

    float dv = g_dinv[warp];
    float av[4];
    upk2(acc0, av[0], av[1]);
    upk2(acc1, av[2], av[3]);
    float4 gm = __ldg((const float4*)(gamma) + lane);
    float4 vr = __ldg((const float4*)(var) + lane);
    float4 bi = __ldg((const float4*)(b) + lane);
    float4 mn = __ldg((const float4*)(mean) + lane);
    float4 bt = __ldg((const float4*)(beta) + lane);
    float gmv[4] = {gm.x, gm.y, gm.z, gm.w};
    float vrv[4] = {vr.x, vr.y, vr.z, vr.w};
    float biv[4] = {bi.x, bi.y, bi.z, bi.w};
    float mnv[4] = {mn.x, mn.y, mn.z, mn.w};
    float btv[4] = {bt.x, bt.y, bt.z, bt.w};
    float out[4];
#pragma unroll
    for (int j = 0; j < 4; j++) {
        float scale = gmv[j] * rsqrtf(vrv[j] + BN_EPS);
        float v = av[j] * dv + biv[j];
        v = (v - mnv[j]) * scale + btv[j];
        out[j] = fmaxf(v, 0.f);
    }
    ((float4*)(g_h + (size_t)warp * HID))[lane] =
        make_float4(out[0], out[1], out[2], out[3]);
}

// ---------------- pooling ----------------
__global__ void k_pool(const int* __restrict__ batch, int n) {
    int start = blockIdx.x * 256;
    int end = min(n, start + 256);
    if (start >= n) return;
    int t = threadIdx.x;          // feature column, 128 threads
    int cur = batch[start];
    float acc = 0.f, cnt = 0.f;
    for (int node = start; node < end; node++) {
        int g = batch[node];
        if (g != cur) {
            atomicAdd(&g_sums[cur * HID + t], acc);
            if (t == 0) atomicAdd(&g_cnts[cur], cnt);
            acc = 0.f; cnt = 0.f; cur = g;
        }
        acc += g_h[(size_t)node * HID + t];
        cnt += 1.f;
    }
    atomicAdd(&g_sums[cur * HID + t], acc);
    if (t == 0) atomicAdd(&g_cnts[cur], cnt);
}

// ------- classifier (pocket MLP fused): per-graph block, 192 -> 96 -> 1 -------
__global__ void k_classify(const float* __restrict__ pocket,
                           const float* __restrict__ pw1, const float* __restrict__ pb1,
                           const float* __restrict__ pw2, const float* __restrict__ pb2,
                           const float* __restrict__ cw1, const float* __restrict__ cb1,
                           const float* __restrict__ cw2, const float* __restrict__ cb2,
                           float* __restrict__ out) {
    __shared__ float p1[64];
    __shared__ float emb[192];
    __shared__ float hid[96];
    int g = blockIdx.x;
    int t = threadIdx.x;  // 192 threads
    if (t < 64) {
        float a = pb1[t];
        for (int k = 0; k < 28; k++) a += pocket[k] * pw1[k * 64 + t];
        p1[t] = fmaxf(a, 0.f);
    }
    if (t < 128) {
        float cnt = fmaxf(g_cnts[g], 1.f);
        emb[t] = g_sums[g * HID + t] / cnt;
    }
    __syncthreads();
    if (t >= 128) {
        int c = t - 128;
        float b = pb2[c];
        for (int k = 0; k < 64; k++) b += p1[k] * pw2[k * 64 + c];
        emb[t] = b;
    }
    __syncthreads();
    if (t < 96) {
        float a = cb1[t];
#pragma unroll 4
        for (int c = 0; c < 192; c++) a += emb[c] * cw1[c * 96 + t];
        hid[t] = fmaxf(a, 0.f);
    }
    __syncthreads();
    if (t == 0) {
        float o = cb2[0];
        for (int j = 0; j < 96; j++) o += hid[j] * cw2[j];
        out[g] = o;
    }
}

// ---------------- launch ----------------
extern "C" void kernel_launch(void* const* d_in, const int* in_sizes, int n_in,
                              void* d_out, int out_size) {
    const float* x      = (const float*)d_in[0];
    const int*   ei     = (const int*)  d_in[1];
    const int*   batch  = (const int*)  d_in[2];
    const float* pocket = (const float*)d_in[3];
    const float* W0 = (const float*)d_in[4];
    const float* b0 = (const float*)d_in[5];
    const float* W1 = (const float*)d_in[6];
    const float* b1 = (const float*)d_in[7];
    const float* W2 = (const float*)d_in[8];
    const float* b2 = (const float*)d_in[9];
    const float* bn_gamma = (const float*)d_in[10];
    const float* bn_beta  = (const float*)d_in[11];
    const float* bn_mean  = (const float*)d_in[12];
    const float* bn_var   = (const float*)d_in[13];
    const float* pw1 = (const float*)d_in[14];
    const float* pb1 = (const float*)d_in[15];
    const float* pw2 = (const float*)d_in[16];
    const float* pb2 = (const float*)d_in[17];
    const float* cw1 = (const float*)d_in[18];
    const float* cb1 = (const float*)d_in[19];
    const float* cw2 = (const float*)d_in[20];
    const float* cb2 = (const float*)d_in[21];
    float* out = (float*)d_out;

    int n = in_sizes[0] / 7;       // 100000
    int e = in_sizes[1] / 2;       // 600000
    const int* src = ei;
    const int* dst = ei + e;

    int L = n + 1;
    int NB = (L + 1023) / 1024;    // 98

    // CSR build (by dst); scan1 also emits dinv
    k_zero_rs<<<(L + 255) / 256, 256>>>(L);
    k_hist<<<(e + 255) / 256, 256>>>(dst, e);
    k_scan1<<<NB, 256>>>(L, n);
    k_prep<<<(n * 8 + 255) / 256, 256>>>(x, n);      // needs dinv only
    k_scan2<<<1, 128>>>(NB);
    k_scan3<<<NB, 256>>>(L, n);
    k_fill<<<(e + 255) / 256, 256>>>(src, dst, e);

    int agg_blocks = (n * 32 + 255) / 256;

    // layer 0: fused aggregate(8-dim) + GEMM + BN + ReLU
    k_layer0<<<agg_blocks, 256>>>(W0, b0, bn_gamma, bn_beta, bn_mean, bn_var, n);
    // layer 1
    k_gemm128<<<(n + 127) / 128, 256>>>(W1, n);
    k_aggregate<<<agg_blocks, 256>>>(b1, bn_gamma + HID, bn_beta + HID,
                                     bn_mean + HID, bn_var + HID, n);
    // layer 2
    k_gemm128<<<(n + 127) / 128, 256>>>(W2, n);
    k_aggregate<<<agg_blocks, 256>>>(b2, bn_gamma + 2 * HID, bn_beta + 2 * HID,
                                     bn_mean + 2 * HID, bn_var + 2 * HID, n);

    // pooling + classifier (pocket fused)
    k_pool<<<(n + 255) / 256, 128>>>(batch, n);
    k_classify<<<NG, 192>>>(pocket, pw1, pb1, pw2, pb2,
                            cw1, cb1, cw2, cb2, out);
}

// round 9
// speedup vs baseline: 1.9671x; 1.1083x over previous
#include <cuda_runtime.h>

#define NMAX 100000
#define EMAX 600000
#define HID 128
#define NG 256
#define BN_EPS 1e-5f
#define FULLMASK 0xffffffffu

typedef unsigned long long ull;

// ---------------- scratch (device globals; no allocs allowed) ----------------
__device__ int   g_rowstart[NMAX + 1];  // CSR row offsets (by dst)
__device__ int   g_fill[NMAX];          // fill cursor
__device__ int   g_csr[EMAX];           // src indices grouped by dst
__device__ int   g_bsum[256];           // scan block sums
__device__ float g_dinv[NMAX];
__device__ float g_xs[NMAX * 8];        // x * dinv, padded to 8 floats
__device__ float g_h[NMAX * HID];       // layer activations
__device__ float g_hls[NMAX * HID];     // (h@W) * dinv[row]
__device__ float g_sums[NG * HID];
__device__ float g_cnts[NG];

// ---------------- f32x2 helpers (sm_103a packed fp32 pipe) ----------------
__device__ __forceinline__ ull pk2(float x, float y) {
    ull r;
    asm("mov.b64 %0, {%1, %2};" : "=l"(r) : "f"(x), "f"(y));
    return r;
}
__device__ __forceinline__ void upk2(ull v, float& x, float& y) {
    asm("mov.b64 {%0, %1}, %2;" : "=f"(x), "=f"(y) : "l"(v));
}
__device__ __forceinline__ ull ffma2(ull a, ull b, ull c) {
    ull r;
    asm("fma.rn.f32x2 %0, %1, %2, %3;" : "=l"(r) : "l"(a), "l"(b), "l"(c));
    return r;
}
__device__ __forceinline__ ull fadd2(ull a, ull b) {
    ull r;
    asm("add.rn.f32x2 %0, %1, %2;" : "=l"(r) : "l"(a), "l"(b));
    return r;
}

// ---------------- CSR build ----------------
__global__ void k_zero_rs(int L) {
    int i = blockIdx.x * blockDim.x + threadIdx.x;
    if (i < L) g_rowstart[i] = 0;
}

__global__ void k_hist(const int* __restrict__ dst, int e) {
    int i = blockIdx.x * blockDim.x + threadIdx.x;
    if (i < e) atomicAdd(&g_rowstart[dst[i] + 1], 1);
}

// phase 1: per-block (1024 elems) inclusive scan, in place; block total -> g_bsum
// Fused extras: emits dinv (pre-scan value at idx i+1 = degree of node i),
// writes g_xs = x * dinv (padded to 8), zeros pooling buffers.
__global__ void k_scan1(const float* __restrict__ x, int L, int n) {
    __shared__ int wsum[8];
    __shared__ int woff[8];
    int t = threadIdx.x;
    int base = blockIdx.x * 1024;
    int i0 = base + t * 4;
    int v[4];
#pragma unroll
    for (int j = 0; j < 4; j++) {
        int idx = i0 + j;
        v[j] = (idx < L) ? g_rowstart[idx] : 0;
        if (idx >= 1 && idx <= n) {
            int node = idx - 1;
            float dv = rsqrtf((float)v[j] + 1.f);
            g_dinv[node] = dv;
            float xv[8];
#pragma unroll
            for (int k = 0; k < 7; k++) xv[k] = __ldg(x + node * 7 + k) * dv;
            xv[7] = 0.f;
            float4* dst4 = (float4*)(g_xs + (size_t)node * 8);
            dst4[0] = make_float4(xv[0], xv[1], xv[2], xv[3]);
            dst4[1] = make_float4(xv[4], xv[5], xv[6], xv[7]);
        }
    }
    // zero pooling buffers (grid covers 25088 threads; NG*HID = 32768)
    int gid = blockIdx.x * blockDim.x + t;
    int stride = gridDim.x * blockDim.x;
    for (int z = gid; z < NG * HID; z += stride) g_sums[z] = 0.f;
    if (gid < NG) g_cnts[gid] = 0.f;

    v[1] += v[0]; v[2] += v[1]; v[3] += v[2];
    int tsum = v[3];
    int lane = t & 31, w = t >> 5;
    int xsc = tsum;
#pragma unroll
    for (int o = 1; o < 32; o <<= 1) {
        int y = __shfl_up_sync(FULLMASK, xsc, o);
        if (lane >= o) xsc += y;
    }
    if (lane == 31) wsum[w] = xsc;
    __syncthreads();
    if (t == 0) {
        int s = 0;
        for (int k = 0; k < 8; k++) { woff[k] = s; s += wsum[k]; }
        g_bsum[blockIdx.x] = s;
    }
    __syncthreads();
    int ex = woff[w] + xsc - tsum;
#pragma unroll
    for (int j = 0; j < 4; j++)
        if (i0 + j < L) g_rowstart[i0 + j] = ex + v[j];
}

// phase 2: single block exclusive scan of block sums (nb <= 128)
__global__ void k_scan2(int nb) {
    __shared__ int wsum[4];
    __shared__ int woff[4];
    int t = threadIdx.x;
    int v = (t < nb) ? g_bsum[t] : 0;
    int lane = t & 31, w = t >> 5;
    int x = v;
#pragma unroll
    for (int o = 1; o < 32; o <<= 1) {
        int y = __shfl_up_sync(FULLMASK, x, o);
        if (lane >= o) x += y;
    }
    if (lane == 31) wsum[w] = x;
    __syncthreads();
    if (t == 0) {
        int s = 0;
        for (int k = 0; k < 4; k++) { woff[k] = s; s += wsum[k]; }
    }
    __syncthreads();
    if (t < nb) g_bsum[t] = woff[w] + x - v;
}

// phase 3: add block offsets; seed g_fill with row starts
__global__ void k_scan3(int L, int n) {
    int t = threadIdx.x;
    int base = blockIdx.x * 1024;
    int off = g_bsum[blockIdx.x];
    int i0 = base + t * 4;
#pragma unroll
    for (int j = 0; j < 4; j++) {
        int idx = i0 + j;
        if (idx < L) {
            int val = g_rowstart[idx] + off;
            g_rowstart[idx] = val;
            if (idx < n) g_fill[idx] = val;
        }
    }
}

__global__ void k_fill(const int* __restrict__ src, const int* __restrict__ dst, int e) {
    int i = blockIdx.x * blockDim.x + threadIdx.x;
    if (i < e) {
        int pos = atomicAdd(&g_fill[dst[i]], 1);
        g_csr[pos] = src[i];
    }
}

// ---- layer 0 fused: aggregate xs (8-dim) -> GEMM 8x128 -> BN -> ReLU -> g_h ----
// one warp per dst node. gather: 16 edges/iter, 2 lanes per edge (float4 each).
__global__ void k_layer0(const float* __restrict__ W0, const float* __restrict__ b0,
                         const float* __restrict__ gamma, const float* __restrict__ beta,
                         const float* __restrict__ mean, const float* __restrict__ var,
                         int n) {
    __shared__ float sW[8 * 128];   // row 7 zero-padded
    for (int i = threadIdx.x; i < 8 * 128; i += blockDim.x)
        sW[i] = (i < 7 * 128) ? W0[i] : 0.f;
    __syncthreads();

    int warp = (blockIdx.x * blockDim.x + threadIdx.x) >> 5;
    int lane = threadIdx.x & 31;
    if (warp >= n) return;

    int s0 = g_rowstart[warp];
    int s1 = g_rowstart[warp + 1];
    float dv = g_dinv[warp];
    int half = lane & 1;            // which float4 of the 8-float row
    int sub = lane >> 1;            // edge slot 0..15

    float4 acc = make_float4(0.f, 0.f, 0.f, 0.f);
    for (int j0 = s0; j0 < s1; j0 += 32) {
        int myidx = (j0 + lane < s1) ? __ldg(&g_csr[j0 + lane]) : 0;
        int m = min(32, s1 - j0);
#pragma unroll
        for (int base = 0; base < 32; base += 16) {
            if (base >= m) break;
            int e = base + sub;
            int s = __shfl_sync(FULLMASK, myidx, e);
            if (e < m) {
                float4 v = __ldg((const float4*)(g_xs + (size_t)s * 8) + half);
                acc.x += v.x; acc.y += v.y; acc.z += v.z; acc.w += v.w;
            }
        }
    }
    // reduce across lanes of same parity (16 lanes each)
#pragma unroll
    for (int off = 2; off < 32; off <<= 1) {
        acc.x += __shfl_down_sync(FULLMASK, acc.x, off);
        acc.y += __shfl_down_sync(FULLMASK, acc.y, off);
        acc.z += __shfl_down_sync(FULLMASK, acc.z, off);
        acc.w += __shfl_down_sync(FULLMASK, acc.w, off);
    }
    // lanes 0,1 hold halves; add self term (xs[dst], one dv already folded)
    // total = (sum_neighbors xs + xs[dst]) * dinv[dst]
    if (lane < 2) {
        float4 self = __ldg((const float4*)(g_xs + (size_t)warp * 8) + lane);
        acc.x = (acc.x + self.x) * dv;
        acc.y = (acc.y + self.y) * dv;
        acc.z = (acc.z + self.z) * dv;
        acc.w = (acc.w + self.w) * dv;
    }
    // broadcast the 8 aggregated values to all lanes
    float xa[8];
    xa[0] = __shfl_sync(FULLMASK, acc.x, 0);
    xa[1] = __shfl_sync(FULLMASK, acc.y, 0);
    xa[2] = __shfl_sync(FULLMASK, acc.z, 0);
    xa[3] = __shfl_sync(FULLMASK, acc.w, 0);
    xa[4] = __shfl_sync(FULLMASK, acc.x, 1);
    xa[5] = __shfl_sync(FULLMASK, acc.y, 1);
    xa[6] = __shfl_sync(FULLMASK, acc.z, 1);
    xa[7] = __shfl_sync(FULLMASK, acc.w, 1);

    // GEMM: 8 x 128, lane covers 4 columns
    float4 r = make_float4(0.f, 0.f, 0.f, 0.f);
#pragma unroll
    for (int k = 0; k < 8; k++) {
        float4 w = ((const float4*)(sW + k * 128))[lane];
        r.x += xa[k] * w.x; r.y += xa[k] * w.y;
        r.z += xa[k] * w.z; r.w += xa[k] * w.w;
    }
    // + bias, BN, ReLU
    float4 gm = __ldg((const float4*)gamma + lane);
    float4 vr = __ldg((const float4*)var + lane);
    float4 bi = __ldg((const float4*)b0 + lane);
    float4 mn = __ldg((const float4*)mean + lane);
    float4 bt = __ldg((const float4*)beta + lane);
    float rv[4] = {r.x, r.y, r.z, r.w};
    float gmv[4] = {gm.x, gm.y, gm.z, gm.w};
    float vrv[4] = {vr.x, vr.y, vr.z, vr.w};
    float biv[4] = {bi.x, bi.y, bi.z, bi.w};
    float mnv[4] = {mn.x, mn.y, mn.z, mn.w};
    float btv[4] = {bt.x, bt.y, bt.z, bt.w};
    float out[4];
#pragma unroll
    for (int j = 0; j < 4; j++) {
        float scale = gmv[j] * rsqrtf(vrv[j] + BN_EPS);
        float v = rv[j] + biv[j];
        v = (v - mnv[j]) * scale + btv[j];
        out[j] = fmaxf(v, 0.f);
    }
    ((float4*)(g_h + (size_t)warp * HID))[lane] =
        make_float4(out[0], out[1], out[2], out[3]);
}

// ---- 128x128 GEMM: g_h @ W, scaled by dinv, f32x2, 128-row tiles ----
__global__ __launch_bounds__(256, 2) void k_gemm128(const float* __restrict__ W, int n) {
    __shared__ float sW[32][128];
    __shared__ float sA[32][132];   // stride 132: 16B-aligned rows for LDS.128

    const float* __restrict__ A = g_h;

    int row0 = blockIdx.x * 128;
    int tid = threadIdx.x;
    int lane = tid & 31, warp = tid >> 5;

    ull acc2[8][4];
#pragma unroll
    for (int p = 0; p < 8; p++)
#pragma unroll
        for (int j = 0; j < 4; j++) acc2[p][j] = 0ull;

    for (int kt = 0; kt < 128; kt += 32) {
        const float4* Wv = (const float4*)(W + kt * 128);
        float4* sWv = (float4*)(&sW[0][0]);
#pragma unroll
        for (int i = 0; i < 4; i++) sWv[tid + 256 * i] = Wv[tid + 256 * i];
#pragma unroll
        for (int i = 0; i < 4; i++) {
            int idx = tid + 256 * i;
            int r = idx >> 3, c = idx & 7;
            int row = row0 + r;
            float4 v = make_float4(0.f, 0.f, 0.f, 0.f);
            if (row < n) v = ((const float4*)(A + (size_t)row * 128 + kt))[c];
            sA[c * 4 + 0][r] = v.x; sA[c * 4 + 1][r] = v.y;
            sA[c * 4 + 2][r] = v.z; sA[c * 4 + 3][r] = v.w;
        }
        __syncthreads();
#pragma unroll 8
        for (int k = 0; k < 32; k++) {
            float4 b = ((const float4*)(&sW[k][0]))[lane];
            ull bb0 = pk2(b.x, b.x), bb1 = pk2(b.y, b.y);
            ull bb2 = pk2(b.z, b.z), bb3 = pk2(b.w, b.w);
            const ull* ap = (const ull*)(&sA[k][warp * 16]);
#pragma unroll
            for (int p = 0; p < 8; p++) {
                ull a = ap[p];
                acc2[p][0] = ffma2(a, bb0, acc2[p][0]);
                acc2[p][1] = ffma2(a, bb1, acc2[p][1]);
                acc2[p][2] = ffma2(a, bb2, acc2[p][2]);
                acc2[p][3] = ffma2(a, bb3, acc2[p][3]);
            }
        }
        __syncthreads();
    }
#pragma unroll
    for (int p = 0; p < 8; p++) {
        float lo[4], hi[4];
#pragma unroll
        for (int j = 0; j < 4; j++) upk2(acc2[p][j], lo[j], hi[j]);
        int r0 = row0 + warp * 16 + 2 * p;
        int r1 = r0 + 1;
        if (r0 < n) {
            float dv = g_dinv[r0];
            ((float4*)(g_hls + (size_t)r0 * HID))[lane] =
                make_float4(lo[0] * dv, lo[1] * dv, lo[2] * dv, lo[3] * dv);
        }
        if (r1 < n) {
            float dv = g_dinv[r1];
            ((float4*)(g_hls + (size_t)r1 * HID))[lane] =
                make_float4(hi[0] * dv, hi[1] * dv, hi[2] * dv, hi[3] * dv);
        }
    }
}

// ------- fused gather-aggregate + BN + ReLU, 8-edge unrolled, f32x2 adds -------
__global__ void k_aggregate(const float* __restrict__ b, const float* __restrict__ gamma,
                            const float* __restrict__ beta, const float* __restrict__ mean,
                            const float* __restrict__ var, int n) {
    int warp = (blockIdx.x * blockDim.x + threadIdx.x) >> 5;
    int lane = threadIdx.x & 31;
    if (warp >= n) return;

    int s0 = g_rowstart[warp];
    int s1 = g_rowstart[warp + 1];

    union F4 { float4 f; ull u[2]; };

    F4 self; self.f = __ldg((const float4*)(g_hls + (size_t)warp * HID) + lane);
    ull acc0 = self.u[0], acc1 = self.u[1];

    for (int j0 = s0; j0 < s1; j0 += 32) {
        int myidx = (j0 + lane < s1) ? __ldg(&g_csr[j0 + lane]) : 0;
        int m = min(32, s1 - j0);
        int j = 0;
        for (; j + 8 <= m; j += 8) {
            int ia[8];
#pragma unroll
            for (int q = 0; q < 8; q++) ia[q] = __shfl_sync(FULLMASK, myidx, j + q);
            F4 v[8];
#pragma unroll
            for (int q = 0; q < 8; q++)
                v[q].f = __ldg((const float4*)(g_hls + (size_t)ia[q] * HID) + lane);
            // tree reduce 8 -> acc
            ull s00 = fadd2(v[0].u[0], v[1].u[0]);
            ull s01 = fadd2(v[2].u[0], v[3].u[0]);
            ull s02 = fadd2(v[4].u[0], v[5].u[0]);
            ull s03 = fadd2(v[6].u[0], v[7].u[0]);
            ull s10 = fadd2(v[0].u[1], v[1].u[1]);
            ull s11 = fadd2(v[2].u[1], v[3].u[1]);
            ull s12 = fadd2(v[4].u[1], v[5].u[1]);
            ull s13 = fadd2(v[6].u[1], v[7].u[1]);
            acc0 = fadd2(acc0, fadd2(fadd2(s00, s01), fadd2(s02, s03)));
            acc1 = fadd2(acc1, fadd2(fadd2(s10, s11), fadd2(s12, s13)));
        }
        for (; j + 4 <= m; j += 4) {
            int i0 = __shfl_sync(FULLMASK, myidx, j);
            int i1 = __shfl_sync(FULLMASK, myidx, j + 1);
            int i2 = __shfl_sync(FULLMASK, myidx, j + 2);
            int i3 = __shfl_sync(FULLMASK, myidx, j + 3);
            F4 v0, v1, v2, v3;
            v0.f = __ldg((const float4*)(g_hls + (size_t)i0 * HID) + lane);
            v1.f = __ldg((const float4*)(g_hls + (size_t)i1 * HID) + lane);
            v2.f = __ldg((const float4*)(g_hls + (size_t)i2 * HID) + lane);
            v3.f = __ldg((const float4*)(g_hls + (size_t)i3 * HID) + lane);
            acc0 = fadd2(acc0, fadd2(v0.u[0], v1.u[0]));
            acc1 = fadd2(acc1, fadd2(v0.u[1], v1.u[1]));
            acc0 = fadd2(acc0, fadd2(v2.u[0], v3.u[0]));
            acc1 = fadd2(acc1, fadd2(v2.u[1], v3.u[1]));
        }
        for (; j < m; j++) {
            int s = __shfl_sync(FULLMASK, myidx, j);
            F4 v; v.f = __ldg((const float4*)(g_hls + (size_t)s * HID) + lane);
            acc0 = fadd2(acc0, v.u[0]);
            acc1 = fadd2(acc1, v.u[1]);
        }
    }

    float dv = g_dinv[warp];
    float av[4];
    upk2(acc0, av[0], av[1]);
    upk2(acc1, av[2], av[3]);
    float4 gm = __ldg((const float4*)(gamma) + lane);
    float4 vr = __ldg((const float4*)(var) + lane);
    float4 bi = __ldg((const float4*)(b) + lane);
    float4 mn = __ldg((const float4*)(mean) + lane);
    float4 bt = __ldg((const float4*)(beta) + lane);
    float gmv[4] = {gm.x, gm.y, gm.z, gm.w};
    float vrv[4] = {vr.x, vr.y, vr.z, vr.w};
    float biv[4] = {bi.x, bi.y, bi.z, bi.w};
    float mnv[4] = {mn.x, mn.y, mn.z, mn.w};
    float btv[4] = {bt.x, bt.y, bt.z, bt.w};
    float out[4];
#pragma unroll
    for (int j = 0; j < 4; j++) {
        float scale = gmv[j] * rsqrtf(vrv[j] + BN_EPS);
        float v = av[j] * dv + biv[j];
        v = (v - mnv[j]) * scale + btv[j];
        out[j] = fmaxf(v, 0.f);
    }
    ((float4*)(g_h + (size_t)warp * HID))[lane] =
        make_float4(out[0], out[1], out[2], out[3]);
}

// ---------------- pooling (128 nodes per block) ----------------
__global__ void k_pool(const int* __restrict__ batch, int n) {
    int start = blockIdx.x * 128;
    int end = min(n, start + 128);
    if (start >= n) return;
    int t = threadIdx.x;          // feature column, 128 threads
    int cur = batch[start];
    float acc = 0.f, cnt = 0.f;
    for (int node = start; node < end; node++) {
        int g = batch[node];
        if (g != cur) {
            atomicAdd(&g_sums[cur * HID + t], acc);
            if (t == 0) atomicAdd(&g_cnts[cur], cnt);
            acc = 0.f; cnt = 0.f; cur = g;
        }
        acc += g_h[(size_t)node * HID + t];
        cnt += 1.f;
    }
    atomicAdd(&g_sums[cur * HID + t], acc);
    if (t == 0) atomicAdd(&g_cnts[cur], cnt);
}

// ------- classifier (pocket MLP fused): per-graph block, 192 -> 96 -> 1 -------
__global__ void k_classify(const float* __restrict__ pocket,
                           const float* __restrict__ pw1, const float* __restrict__ pb1,
                           const float* __restrict__ pw2, const float* __restrict__ pb2,
                           const float* __restrict__ cw1, const float* __restrict__ cb1,
                           const float* __restrict__ cw2, const float* __restrict__ cb2,
                           float* __restrict__ out) {
    __shared__ float p1[64];
    __shared__ float emb[192];
    __shared__ float hid[96];
    int g = blockIdx.x;
    int t = threadIdx.x;  // 192 threads
    if (t < 64) {
        float a = pb1[t];
        for (int k = 0; k < 28; k++) a += pocket[k] * pw1[k * 64 + t];
        p1[t] = fmaxf(a, 0.f);
    }
    if (t < 128) {
        float cnt = fmaxf(g_cnts[g], 1.f);
        emb[t] = g_sums[g * HID + t] / cnt;
    }
    __syncthreads();
    if (t >= 128) {
        int c = t - 128;
        float b = pb2[c];
        for (int k = 0; k < 64; k++) b += p1[k] * pw2[k * 64 + c];
        emb[t] = b;
    }
    __syncthreads();
    if (t < 96) {
        float a = cb1[t];
#pragma unroll 4
        for (int c = 0; c < 192; c++) a += emb[c] * cw1[c * 96 + t];
        hid[t] = fmaxf(a, 0.f);
    }
    __syncthreads();
    if (t == 0) {
        float o = cb2[0];
        for (int j = 0; j < 96; j++) o += hid[j] * cw2[j];
        out[g] = o;
    }
}

// ---------------- launch ----------------
extern "C" void kernel_launch(void* const* d_in, const int* in_sizes, int n_in,
                              void* d_out, int out_size) {
    const float* x      = (const float*)d_in[0];
    const int*   ei     = (const int*)  d_in[1];
    const int*   batch  = (const int*)  d_in[2];
    const float* pocket = (const float*)d_in[3];
    const float* W0 = (const float*)d_in[4];
    const float* b0 = (const float*)d_in[5];
    const float* W1 = (const float*)d_in[6];
    const float* b1 = (const float*)d_in[7];
    const float* W2 = (const float*)d_in[8];
    const float* b2 = (const float*)d_in[9];
    const float* bn_gamma = (const float*)d_in[10];
    const float* bn_beta  = (const float*)d_in[11];
    const float* bn_mean  = (const float*)d_in[12];
    const float* bn_var   = (const float*)d_in[13];
    const float* pw1 = (const float*)d_in[14];
    const float* pb1 = (const float*)d_in[15];
    const float* pw2 = (const float*)d_in[16];
    const float* pb2 = (const float*)d_in[17];
    const float* cw1 = (const float*)d_in[18];
    const float* cb1 = (const float*)d_in[19];
    const float* cw2 = (const float*)d_in[20];
    const float* cb2 = (const float*)d_in[21];
    float* out = (float*)d_out;

    int n = in_sizes[0] / 7;       // 100000
    int e = in_sizes[1] / 2;       // 600000
    const int* src = ei;
    const int* dst = ei + e;

    int L = n + 1;
    int NB = (L + 1023) / 1024;    // 98

    // CSR build (by dst); scan1 fuses dinv + xs-prep + pool-zero
    k_zero_rs<<<(L + 255) / 256, 256>>>(L);
    k_hist<<<(e + 255) / 256, 256>>>(dst, e);
    k_scan1<<<NB, 256>>>(x, L, n);
    k_scan2<<<1, 128>>>(NB);
    k_scan3<<<NB, 256>>>(L, n);
    k_fill<<<(e + 255) / 256, 256>>>(src, dst, e);

    int agg_blocks = (n * 32 + 255) / 256;

    // layer 0: fused aggregate(8-dim) + GEMM + BN + ReLU
    k_layer0<<<agg_blocks, 256>>>(W0, b0, bn_gamma, bn_beta, bn_mean, bn_var, n);
    // layer 1
    k_gemm128<<<(n + 127) / 128, 256>>>(W1, n);
    k_aggregate<<<agg_blocks, 256>>>(b1, bn_gamma + HID, bn_beta + HID,
                                     bn_mean + HID, bn_var + HID, n);
    // layer 2
    k_gemm128<<<(n + 127) / 128, 256>>>(W2, n);
    k_aggregate<<<agg_blocks, 256>>>(b2, bn_gamma + 2 * HID, bn_beta + 2 * HID,
                                     bn_mean + 2 * HID, bn_var + 2 * HID, n);

    // pooling + classifier (pocket fused)
    k_pool<<<(n + 127) / 128, 128>>>(batch, n);
    k_classify<<<NG, 192>>>(pocket, pw1, pb1, pw2, pb2,
                            cw1, cb1, cw2, cb2, out);
}

// round 10
// speedup vs baseline: 2.1330x; 1.0844x over previous
#include <cuda_runtime.h>

#define NMAX 100000
#define EMAX 600000
#define HID 128
#define NG 256
#define BN_EPS 1e-5f
#define FULLMASK 0xffffffffu

typedef unsigned long long ull;
typedef unsigned int uint;

// ---------------- scratch (device globals; no allocs allowed) ----------------
__device__ int   g_rowstart[NMAX + 1];  // CSR row offsets (by dst)
__device__ int   g_fill[NMAX];          // fill cursor
__device__ int   g_csr[EMAX];           // src indices grouped by dst
__device__ int   g_bsum[256];           // scan block sums
__device__ float g_dinv[NMAX];
__device__ float g_xs[NMAX * 8];        // x * dinv, padded to 8 floats
__device__ float g_h[NMAX * HID];       // layer activations (fp32)
__device__ unsigned short g_hls[NMAX * HID];  // (h@W)*dinv in bf16 (gather source)
__device__ float g_sums[NG * HID];
__device__ float g_cnts[NG];

// ---------------- f32x2 / bf16 helpers (sm_103a) ----------------
__device__ __forceinline__ ull pk2(float x, float y) {
    ull r;
    asm("mov.b64 %0, {%1, %2};" : "=l"(r) : "f"(x), "f"(y));
    return r;
}
__device__ __forceinline__ void upk2(ull v, float& x, float& y) {
    asm("mov.b64 {%0, %1}, %2;" : "=f"(x), "=f"(y) : "l"(v));
}
__device__ __forceinline__ ull ffma2(ull a, ull b, ull c) {
    ull r;
    asm("fma.rn.f32x2 %0, %1, %2, %3;" : "=l"(r) : "l"(a), "l"(b), "l"(c));
    return r;
}
__device__ __forceinline__ ull fadd2(ull a, ull b) {
    ull r;
    asm("add.rn.f32x2 %0, %1, %2;" : "=l"(r) : "l"(a), "l"(b));
    return r;
}
// pack two f32 into bf16x2: lo -> low half, hi -> high half
__device__ __forceinline__ uint bfpack(float lo, float hi) {
    uint r;
    asm("cvt.rn.bf16x2.f32 %0, %1, %2;" : "=r"(r) : "f"(hi), "f"(lo));
    return r;
}
// unpack bf16x2 (u32) into packed f32x2 pair (exact: bf16 -> f32 is <<16)
__device__ __forceinline__ ull bf2f2(uint u) {
    uint lo = u << 16;
    uint hi = u & 0xffff0000u;
    ull r;
    asm("mov.b64 %0, {%1, %2};" : "=l"(r) : "r"(lo), "r"(hi));
    return r;
}

// ---------------- CSR build ----------------
__global__ void k_zero_rs(int L) {
    int i = blockIdx.x * blockDim.x + threadIdx.x;
    if (i < L) g_rowstart[i] = 0;
}

__global__ void k_hist(const int* __restrict__ dst, int e) {
    int i = blockIdx.x * blockDim.x + threadIdx.x;
    if (i < e) atomicAdd(&g_rowstart[dst[i] + 1], 1);
}

// phase 1: per-block (1024 elems) inclusive scan, in place; block total -> g_bsum
// Fused extras: emits dinv (pre-scan value at idx i+1 = degree of node i),
// writes g_xs = x * dinv (padded to 8), zeros pooling buffers.
__global__ void k_scan1(const float* __restrict__ x, int L, int n) {
    __shared__ int wsum[8];
    __shared__ int woff[8];
    int t = threadIdx.x;
    int base = blockIdx.x * 1024;
    int i0 = base + t * 4;
    int v[4];
#pragma unroll
    for (int j = 0; j < 4; j++) {
        int idx = i0 + j;
        v[j] = (idx < L) ? g_rowstart[idx] : 0;
        if (idx >= 1 && idx <= n) {
            int node = idx - 1;
            float dv = rsqrtf((float)v[j] + 1.f);
            g_dinv[node] = dv;
            float xv[8];
#pragma unroll
            for (int k = 0; k < 7; k++) xv[k] = __ldg(x + node * 7 + k) * dv;
            xv[7] = 0.f;
            float4* dst4 = (float4*)(g_xs + (size_t)node * 8);
            dst4[0] = make_float4(xv[0], xv[1], xv[2], xv[3]);
            dst4[1] = make_float4(xv[4], xv[5], xv[6], xv[7]);
        }
    }
    int gid = blockIdx.x * blockDim.x + t;
    int stride = gridDim.x * blockDim.x;
    for (int z = gid; z < NG * HID; z += stride) g_sums[z] = 0.f;
    if (gid < NG) g_cnts[gid] = 0.f;

    v[1] += v[0]; v[2] += v[1]; v[3] += v[2];
    int tsum = v[3];
    int lane = t & 31, w = t >> 5;
    int xsc = tsum;
#pragma unroll
    for (int o = 1; o < 32; o <<= 1) {
        int y = __shfl_up_sync(FULLMASK, xsc, o);
        if (lane >= o) xsc += y;
    }
    if (lane == 31) wsum[w] = xsc;
    __syncthreads();
    if (t == 0) {
        int s = 0;
        for (int k = 0; k < 8; k++) { woff[k] = s; s += wsum[k]; }
        g_bsum[blockIdx.x] = s;
    }
    __syncthreads();
    int ex = woff[w] + xsc - tsum;
#pragma unroll
    for (int j = 0; j < 4; j++)
        if (i0 + j < L) g_rowstart[i0 + j] = ex + v[j];
}

// phase 2: single block exclusive scan of block sums (nb <= 128)
__global__ void k_scan2(int nb) {
    __shared__ int wsum[4];
    __shared__ int woff[4];
    int t = threadIdx.x;
    int v = (t < nb) ? g_bsum[t] : 0;
    int lane = t & 31, w = t >> 5;
    int x = v;
#pragma unroll
    for (int o = 1; o < 32; o <<= 1) {
        int y = __shfl_up_sync(FULLMASK, x, o);
        if (lane >= o) x += y;
    }
    if (lane == 31) wsum[w] = x;
    __syncthreads();
    if (t == 0) {
        int s = 0;
        for (int k = 0; k < 4; k++) { woff[k] = s; s += wsum[k]; }
    }
    __syncthreads();
    if (t < nb) g_bsum[t] = woff[w] + x - v;
}

// phase 3: add block offsets; seed g_fill with row starts
__global__ void k_scan3(int L, int n) {
    int t = threadIdx.x;
    int base = blockIdx.x * 1024;
    int off = g_bsum[blockIdx.x];
    int i0 = base + t * 4;
#pragma unroll
    for (int j = 0; j < 4; j++) {
        int idx = i0 + j;
        if (idx < L) {
            int val = g_rowstart[idx] + off;
            g_rowstart[idx] = val;
            if (idx < n) g_fill[idx] = val;
        }
    }
}

__global__ void k_fill(const int* __restrict__ src, const int* __restrict__ dst, int e) {
    int i = blockIdx.x * blockDim.x + threadIdx.x;
    if (i < e) {
        int pos = atomicAdd(&g_fill[dst[i]], 1);
        g_csr[pos] = src[i];
    }
}

// ---- layer 0 fused: aggregate xs (8-dim) -> GEMM 8x128 -> BN -> ReLU -> g_h ----
__global__ void k_layer0(const float* __restrict__ W0, const float* __restrict__ b0,
                         const float* __restrict__ gamma, const float* __restrict__ beta,
                         const float* __restrict__ mean, const float* __restrict__ var,
                         int n) {
    __shared__ float sW[8 * 128];   // row 7 zero-padded
    for (int i = threadIdx.x; i < 8 * 128; i += blockDim.x)
        sW[i] = (i < 7 * 128) ? W0[i] : 0.f;
    __syncthreads();

    int warp = (blockIdx.x * blockDim.x + threadIdx.x) >> 5;
    int lane = threadIdx.x & 31;
    if (warp >= n) return;

    int s0 = g_rowstart[warp];
    int s1 = g_rowstart[warp + 1];
    float dv = g_dinv[warp];
    int half = lane & 1;
    int sub = lane >> 1;

    float4 acc = make_float4(0.f, 0.f, 0.f, 0.f);
    for (int j0 = s0; j0 < s1; j0 += 32) {
        int myidx = (j0 + lane < s1) ? __ldg(&g_csr[j0 + lane]) : 0;
        int m = min(32, s1 - j0);
#pragma unroll
        for (int base = 0; base < 32; base += 16) {
            if (base >= m) break;
            int e = base + sub;
            int s = __shfl_sync(FULLMASK, myidx, e);
            if (e < m) {
                float4 v = __ldg((const float4*)(g_xs + (size_t)s * 8) + half);
                acc.x += v.x; acc.y += v.y; acc.z += v.z; acc.w += v.w;
            }
        }
    }
#pragma unroll
    for (int off = 2; off < 32; off <<= 1) {
        acc.x += __shfl_down_sync(FULLMASK, acc.x, off);
        acc.y += __shfl_down_sync(FULLMASK, acc.y, off);
        acc.z += __shfl_down_sync(FULLMASK, acc.z, off);
        acc.w += __shfl_down_sync(FULLMASK, acc.w, off);
    }
    if (lane < 2) {
        float4 self = __ldg((const float4*)(g_xs + (size_t)warp * 8) + lane);
        acc.x = (acc.x + self.x) * dv;
        acc.y = (acc.y + self.y) * dv;
        acc.z = (acc.z + self.z) * dv;
        acc.w = (acc.w + self.w) * dv;
    }
    float xa[8];
    xa[0] = __shfl_sync(FULLMASK, acc.x, 0);
    xa[1] = __shfl_sync(FULLMASK, acc.y, 0);
    xa[2] = __shfl_sync(FULLMASK, acc.z, 0);
    xa[3] = __shfl_sync(FULLMASK, acc.w, 0);
    xa[4] = __shfl_sync(FULLMASK, acc.x, 1);
    xa[5] = __shfl_sync(FULLMASK, acc.y, 1);
    xa[6] = __shfl_sync(FULLMASK, acc.z, 1);
    xa[7] = __shfl_sync(FULLMASK, acc.w, 1);

    float4 r = make_float4(0.f, 0.f, 0.f, 0.f);
#pragma unroll
    for (int k = 0; k < 8; k++) {
        float4 w = ((const float4*)(sW + k * 128))[lane];
        r.x += xa[k] * w.x; r.y += xa[k] * w.y;
        r.z += xa[k] * w.z; r.w += xa[k] * w.w;
    }
    float4 gm = __ldg((const float4*)gamma + lane);
    float4 vr = __ldg((const float4*)var + lane);
    float4 bi = __ldg((const float4*)b0 + lane);
    float4 mn = __ldg((const float4*)mean + lane);
    float4 bt = __ldg((const float4*)beta + lane);
    float rv[4] = {r.x, r.y, r.z, r.w};
    float gmv[4] = {gm.x, gm.y, gm.z, gm.w};
    float vrv[4] = {vr.x, vr.y, vr.z, vr.w};
    float biv[4] = {bi.x, bi.y, bi.z, bi.w};
    float mnv[4] = {mn.x, mn.y, mn.z, mn.w};
    float btv[4] = {bt.x, bt.y, bt.z, bt.w};
    float out[4];
#pragma unroll
    for (int j = 0; j < 4; j++) {
        float scale = gmv[j] * rsqrtf(vrv[j] + BN_EPS);
        float v = rv[j] + biv[j];
        v = (v - mnv[j]) * scale + btv[j];
        out[j] = fmaxf(v, 0.f);
    }
    ((float4*)(g_h + (size_t)warp * HID))[lane] =
        make_float4(out[0], out[1], out[2], out[3]);
}

// ---- 128x128 GEMM: g_h @ W, scaled by dinv, f32x2; bf16 output to g_hls ----
__global__ __launch_bounds__(256, 2) void k_gemm128(const float* __restrict__ W, int n) {
    __shared__ float sW[32][128];
    __shared__ float sA[32][132];   // 16B-aligned rows for LDS.128

    const float* __restrict__ A = g_h;

    int row0 = blockIdx.x * 128;
    int tid = threadIdx.x;
    int lane = tid & 31, warp = tid >> 5;

    ull acc2[8][4];
#pragma unroll
    for (int p = 0; p < 8; p++)
#pragma unroll
        for (int j = 0; j < 4; j++) acc2[p][j] = 0ull;

    for (int kt = 0; kt < 128; kt += 32) {
        const float4* Wv = (const float4*)(W + kt * 128);
        float4* sWv = (float4*)(&sW[0][0]);
#pragma unroll
        for (int i = 0; i < 4; i++) sWv[tid + 256 * i] = Wv[tid + 256 * i];
#pragma unroll
        for (int i = 0; i < 4; i++) {
            int idx = tid + 256 * i;
            int r = idx >> 3, c = idx & 7;
            int row = row0 + r;
            float4 v = make_float4(0.f, 0.f, 0.f, 0.f);
            if (row < n) v = ((const float4*)(A + (size_t)row * 128 + kt))[c];
            sA[c * 4 + 0][r] = v.x; sA[c * 4 + 1][r] = v.y;
            sA[c * 4 + 2][r] = v.z; sA[c * 4 + 3][r] = v.w;
        }
        __syncthreads();
#pragma unroll 8
        for (int k = 0; k < 32; k++) {
            float4 b = ((const float4*)(&sW[k][0]))[lane];
            ull bb0 = pk2(b.x, b.x), bb1 = pk2(b.y, b.y);
            ull bb2 = pk2(b.z, b.z), bb3 = pk2(b.w, b.w);
            const ull* ap = (const ull*)(&sA[k][warp * 16]);
#pragma unroll
            for (int p = 0; p < 8; p++) {
                ull a = ap[p];
                acc2[p][0] = ffma2(a, bb0, acc2[p][0]);
                acc2[p][1] = ffma2(a, bb1, acc2[p][1]);
                acc2[p][2] = ffma2(a, bb2, acc2[p][2]);
                acc2[p][3] = ffma2(a, bb3, acc2[p][3]);
            }
        }
        __syncthreads();
    }
#pragma unroll
    for (int p = 0; p < 8; p++) {
        float lo[4], hi[4];
#pragma unroll
        for (int j = 0; j < 4; j++) upk2(acc2[p][j], lo[j], hi[j]);
        int r0 = row0 + warp * 16 + 2 * p;
        int r1 = r0 + 1;
        if (r0 < n) {
            float dv = g_dinv[r0];
            uint p0 = bfpack(lo[0] * dv, lo[1] * dv);
            uint p1 = bfpack(lo[2] * dv, lo[3] * dv);
            ((uint2*)(g_hls + (size_t)r0 * HID))[lane] = make_uint2(p0, p1);
        }
        if (r1 < n) {
            float dv = g_dinv[r1];
            uint p0 = bfpack(hi[0] * dv, hi[1] * dv);
            uint p1 = bfpack(hi[2] * dv, hi[3] * dv);
            ((uint2*)(g_hls + (size_t)r1 * HID))[lane] = make_uint2(p0, p1);
        }
    }
}

// ------- fused gather-aggregate + BN + ReLU; bf16 gather, fp32 accumulate -------
// one warp per dst node; lane covers 4 columns (uint2 = 4 bf16)
__global__ void k_aggregate(const float* __restrict__ b, const float* __restrict__ gamma,
                            const float* __restrict__ beta, const float* __restrict__ mean,
                            const float* __restrict__ var, int n) {
    int warp = (blockIdx.x * blockDim.x + threadIdx.x) >> 5;
    int lane = threadIdx.x & 31;
    if (warp >= n) return;

    int s0 = g_rowstart[warp];
    int s1 = g_rowstart[warp + 1];

    // self term
    uint2 sv = __ldg((const uint2*)(g_hls + (size_t)warp * HID) + lane);
    ull acc0 = bf2f2(sv.x), acc1 = bf2f2(sv.y);

    for (int j0 = s0; j0 < s1; j0 += 32) {
        int myidx = (j0 + lane < s1) ? __ldg(&g_csr[j0 + lane]) : 0;
        int m = min(32, s1 - j0);
        int j = 0;
        for (; j + 8 <= m; j += 8) {
            int ia[8];
#pragma unroll
            for (int q = 0; q < 8; q++) ia[q] = __shfl_sync(FULLMASK, myidx, j + q);
            uint2 v[8];
#pragma unroll
            for (int q = 0; q < 8; q++)
                v[q] = __ldg((const uint2*)(g_hls + (size_t)ia[q] * HID) + lane);
#pragma unroll
            for (int q = 0; q < 8; q++) {
                acc0 = fadd2(acc0, bf2f2(v[q].x));
                acc1 = fadd2(acc1, bf2f2(v[q].y));
            }
        }
        for (; j + 4 <= m; j += 4) {
            int i0 = __shfl_sync(FULLMASK, myidx, j);
            int i1 = __shfl_sync(FULLMASK, myidx, j + 1);
            int i2 = __shfl_sync(FULLMASK, myidx, j + 2);
            int i3 = __shfl_sync(FULLMASK, myidx, j + 3);
            uint2 v0 = __ldg((const uint2*)(g_hls + (size_t)i0 * HID) + lane);
            uint2 v1 = __ldg((const uint2*)(g_hls + (size_t)i1 * HID) + lane);
            uint2 v2 = __ldg((const uint2*)(g_hls + (size_t)i2 * HID) + lane);
            uint2 v3 = __ldg((const uint2*)(g_hls + (size_t)i3 * HID) + lane);
            acc0 = fadd2(acc0, fadd2(bf2f2(v0.x), bf2f2(v1.x)));
            acc1 = fadd2(acc1, fadd2(bf2f2(v0.y), bf2f2(v1.y)));
            acc0 = fadd2(acc0, fadd2(bf2f2(v2.x), bf2f2(v3.x)));
            acc1 = fadd2(acc1, fadd2(bf2f2(v2.y), bf2f2(v3.y)));
        }
        for (; j < m; j++) {
            int s = __shfl_sync(FULLMASK, myidx, j);
            uint2 v = __ldg((const uint2*)(g_hls + (size_t)s * HID) + lane);
            acc0 = fadd2(acc0, bf2f2(v.x));
            acc1 = fadd2(acc1, bf2f2(v.y));
        }
    }

    float dv = g_dinv[warp];
    float av[4];
    upk2(acc0, av[0], av[1]);
    upk2(acc1, av[2], av[3]);
    float4 gm = __ldg((const float4*)(gamma) + lane);
    float4 vr = __ldg((const float4*)(var) + lane);
    float4 bi = __ldg((const float4*)(b) + lane);
    float4 mn = __ldg((const float4*)(mean) + lane);
    float4 bt = __ldg((const float4*)(beta) + lane);
    float gmv[4] = {gm.x, gm.y, gm.z, gm.w};
    float vrv[4] = {vr.x, vr.y, vr.z, vr.w};
    float biv[4] = {bi.x, bi.y, bi.z, bi.w};
    float mnv[4] = {mn.x, mn.y, mn.z, mn.w};
    float btv[4] = {bt.x, bt.y, bt.z, bt.w};
    float out[4];
#pragma unroll
    for (int j = 0; j < 4; j++) {
        float scale = gmv[j] * rsqrtf(vrv[j] + BN_EPS);
        float v = av[j] * dv + biv[j];
        v = (v - mnv[j]) * scale + btv[j];
        out[j] = fmaxf(v, 0.f);
    }
    ((float4*)(g_h + (size_t)warp * HID))[lane] =
        make_float4(out[0], out[1], out[2], out[3]);
}

// ---------------- pooling (128 nodes per block) ----------------
__global__ void k_pool(const int* __restrict__ batch, int n) {
    int start = blockIdx.x * 128;
    int end = min(n, start + 128);
    if (start >= n) return;
    int t = threadIdx.x;          // feature column, 128 threads
    int cur = batch[start];
    float acc = 0.f, cnt = 0.f;
    for (int node = start; node < end; node++) {
        int g = batch[node];
        if (g != cur) {
            atomicAdd(&g_sums[cur * HID + t], acc);
            if (t == 0) atomicAdd(&g_cnts[cur], cnt);
            acc = 0.f; cnt = 0.f; cur = g;
        }
        acc += g_h[(size_t)node * HID + t];
        cnt += 1.f;
    }
    atomicAdd(&g_sums[cur * HID + t], acc);
    if (t == 0) atomicAdd(&g_cnts[cur], cnt);
}

// ------- classifier (pocket MLP fused): per-graph block, 192 -> 96 -> 1 -------
__global__ void k_classify(const float* __restrict__ pocket,
                           const float* __restrict__ pw1, const float* __restrict__ pb1,
                           const float* __restrict__ pw2, const float* __restrict__ pb2,
                           const float* __restrict__ cw1, const float* __restrict__ cb1,
                           const float* __restrict__ cw2, const float* __restrict__ cb2,
                           float* __restrict__ out) {
    __shared__ float p1[64];
    __shared__ float emb[192];
    __shared__ float hid[96];
    int g = blockIdx.x;
    int t = threadIdx.x;  // 192 threads
    if (t < 64) {
        float a = pb1[t];
        for (int k = 0; k < 28; k++) a += pocket[k] * pw1[k * 64 + t];
        p1[t] = fmaxf(a, 0.f);
    }
    if (t < 128) {
        float cnt = fmaxf(g_cnts[g], 1.f);
        emb[t] = g_sums[g * HID + t] / cnt;
    }
    __syncthreads();
    if (t >= 128) {
        int c = t - 128;
        float b = pb2[c];
        for (int k = 0; k < 64; k++) b += p1[k] * pw2[k * 64 + c];
        emb[t] = b;
    }
    __syncthreads();
    if (t < 96) {
        float a = cb1[t];
#pragma unroll 4
        for (int c = 0; c < 192; c++) a += emb[c] * cw1[c * 96 + t];
        hid[t] = fmaxf(a, 0.f);
    }
    __syncthreads();
    if (t == 0) {
        float o = cb2[0];
        for (int j = 0; j < 96; j++) o += hid[j] * cw2[j];
        out[g] = o;
    }
}

// ---------------- launch ----------------
extern "C" void kernel_launch(void* const* d_in, const int* in_sizes, int n_in,
                              void* d_out, int out_size) {
    const float* x      = (const float*)d_in[0];
    const int*   ei     = (const int*)  d_in[1];
    const int*   batch  = (const int*)  d_in[2];
    const float* pocket = (const float*)d_in[3];
    const float* W0 = (const float*)d_in[4];
    const float* b0 = (const float*)d_in[5];
    const float* W1 = (const float*)d_in[6];
    const float* b1 = (const float*)d_in[7];
    const float* W2 = (const float*)d_in[8];
    const float* b2 = (const float*)d_in[9];
    const float* bn_gamma = (const float*)d_in[10];
    const float* bn_beta  = (const float*)d_in[11];
    const float* bn_mean  = (const float*)d_in[12];
    const float* bn_var   = (const float*)d_in[13];
    const float* pw1 = (const float*)d_in[14];
    const float* pb1 = (const float*)d_in[15];
    const float* pw2 = (const float*)d_in[16];
    const float* pb2 = (const float*)d_in[17];
    const float* cw1 = (const float*)d_in[18];
    const float* cb1 = (const float*)d_in[19];
    const float* cw2 = (const float*)d_in[20];
    const float* cb2 = (const float*)d_in[21];
    float* out = (float*)d_out;

    int n = in_sizes[0] / 7;       // 100000
    int e = in_sizes[1] / 2;       // 600000
    const int* src = ei;
    const int* dst = ei + e;

    int L = n + 1;
    int NB = (L + 1023) / 1024;    // 98

    // CSR build (by dst); scan1 fuses dinv + xs-prep + pool-zero
    k_zero_rs<<<(L + 255) / 256, 256>>>(L);
    k_hist<<<(e + 255) / 256, 256>>>(dst, e);
    k_scan1<<<NB, 256>>>(x, L, n);
    k_scan2<<<1, 128>>>(NB);
    k_scan3<<<NB, 256>>>(L, n);
    k_fill<<<(e + 255) / 256, 256>>>(src, dst, e);

    int agg_blocks = (n * 32 + 255) / 256;

    // layer 0: fused aggregate(8-dim) + GEMM + BN + ReLU
    k_layer0<<<agg_blocks, 256>>>(W0, b0, bn_gamma, bn_beta, bn_mean, bn_var, n);
    // layer 1
    k_gemm128<<<(n + 127) / 128, 256>>>(W1, n);
    k_aggregate<<<agg_blocks, 256>>>(b1, bn_gamma + HID, bn_beta + HID,
                                     bn_mean + HID, bn_var + HID, n);
    // layer 2
    k_gemm128<<<(n + 127) / 128, 256>>>(W2, n);
    k_aggregate<<<agg_blocks, 256>>>(b2, bn_gamma + 2 * HID, bn_beta + 2 * HID,
                                     bn_mean + 2 * HID, bn_var + 2 * HID, n);

    // pooling + classifier (pocket fused)
    k_pool<<<(n + 127) / 128, 128>>>(batch, n);
    k_classify<<<NG, 192>>>(pocket, pw1, pb1, pw2, pb2,
                            cw1, cb1, cw2, cb2, out);
}